// round 2
// baseline (speedup 1.0000x reference)
#include <cuda_runtime.h>

#define NN 100000
#define CC 128
#define EE 600000
#define HIDDEN 512

// ---------------- scratch (device globals; no allocations allowed) ----------
__device__ float g_h[(size_t)NN * CC];
__device__ float g_Q[(size_t)NN * CC];
__device__ float g_K[(size_t)NN * CC];
__device__ float g_V[(size_t)NN * CC];
__device__ float g_aggr[(size_t)NN * CC];
__device__ float g_x2[(size_t)NN * CC];
__device__ float g_hidden[(size_t)NN * HIDDEN];

// ---------------- LayerNorm: one warp per row (C=128 -> float4/lane) --------
__global__ void ln_kernel(const float* __restrict__ x,
                          const float* __restrict__ g,
                          const float* __restrict__ b,
                          float* __restrict__ out) {
    int row  = blockIdx.x * 8 + (threadIdx.x >> 5);
    int lane = threadIdx.x & 31;
    if (row >= NN) return;
    float4 v = *(const float4*)&x[(size_t)row * CC + lane * 4];
    float s  = v.x + v.y + v.z + v.w;
    float ss = v.x * v.x + v.y * v.y + v.z * v.z + v.w * v.w;
#pragma unroll
    for (int d = 16; d; d >>= 1) {
        s  += __shfl_xor_sync(0xffffffffu, s, d);
        ss += __shfl_xor_sync(0xffffffffu, ss, d);
    }
    float mu  = s * (1.0f / CC);
    float var = ss * (1.0f / CC) - mu * mu;
    float inv = rsqrtf(var + 1e-5f);
    float4 gg = *(const float4*)&g[lane * 4];
    float4 bb = *(const float4*)&b[lane * 4];
    float4 o;
    o.x = (v.x - mu) * inv * gg.x + bb.x;
    o.y = (v.y - mu) * inv * gg.y + bb.y;
    o.z = (v.z - mu) * inv * gg.z + bb.z;
    o.w = (v.w - mu) * inv * gg.w + bb.w;
    *(float4*)&out[(size_t)row * CC + lane * 4] = o;
}

// ---------------- zero-fill -------------------------------------------------
__global__ void zero_kernel(float4* __restrict__ p, size_t n4) {
    size_t i      = (size_t)blockIdx.x * blockDim.x + threadIdx.x;
    size_t stride = (size_t)gridDim.x * blockDim.x;
    float4 z = make_float4(0.f, 0.f, 0.f, 0.f);
    for (; i < n4; i += stride) p[i] = z;
}

// ---------------- per-edge attention: one warp per edge ---------------------
// lane l covers channels [4l, 4l+4); head = l/4 (HD=16 -> 4 lanes per head)
// edge_index arrives as int32 (harness converts int64 -> int32).
__global__ void edge_kernel(const int* __restrict__ ei,
                            const float* __restrict__ Q,
                            const float* __restrict__ K,
                            const float* __restrict__ V,
                            float* __restrict__ aggr) {
    int e    = (int)(((size_t)blockIdx.x * blockDim.x + threadIdx.x) >> 5);
    int lane = threadIdx.x & 31;
    if (e >= EE) return;
    int src = ei[e];
    int dst = ei[EE + e];

    float4 q = *(const float4*)&Q[(size_t)dst * CC + lane * 4];
    float4 k = *(const float4*)&K[(size_t)src * CC + lane * 4];
    float4 v = *(const float4*)&V[(size_t)src * CC + lane * 4];

    // per-head dot product (4 lanes per head)
    float p = q.x * k.x + q.y * k.y + q.z * k.z + q.w * k.w;
    p += __shfl_xor_sync(0xffffffffu, p, 1);
    p += __shfl_xor_sync(0xffffffffu, p, 2);
    float s = p * 0.25f;  // 1/sqrt(HD=16)

    // softmax over 8 heads: butterfly across head groups (xor 4,8,16)
    float m = s;
    m = fmaxf(m, __shfl_xor_sync(0xffffffffu, m, 4));
    m = fmaxf(m, __shfl_xor_sync(0xffffffffu, m, 8));
    m = fmaxf(m, __shfl_xor_sync(0xffffffffu, m, 16));
    float ex = __expf(s - m);
    float sum = ex;
    sum += __shfl_xor_sync(0xffffffffu, sum, 4);
    sum += __shfl_xor_sync(0xffffffffu, sum, 8);
    sum += __shfl_xor_sync(0xffffffffu, sum, 16);
    float a = ex / sum;

    float* base = &aggr[(size_t)dst * CC + lane * 4];
    atomicAdd(base + 0, v.x * a);
    atomicAdd(base + 1, v.y * a);
    atomicAdd(base + 2, v.z * a);
    atomicAdd(base + 3, v.w * a);
}

// ---------------- tiled fp32 GEMM: out = act(A@B + bias) [+ resid] ----------
// BM=64, BN=128, BK=128, 256 threads, 4x8 register tile.
// Thread (tr,tc): rows tr*4+i, cols tc + 16*j (conflict-free Bs reads).
template <bool RELU, bool RESID>
__global__ void gemm_kernel(const float* __restrict__ A, int lda,
                            const float* __restrict__ B, int ldb,
                            const float* __restrict__ bias,
                            const float* __restrict__ resid,
                            float* __restrict__ out, int ldo,
                            int M, int Ktot) {
    extern __shared__ float smem[];
    const int BNP = 132;                 // padded row for Bs
    float* As = smem;                    // [64][128]
    float* Bs = smem + 64 * 128;         // [128][BNP]

    int row0 = blockIdx.x * 64;
    int col0 = blockIdx.y * 128;
    int tid  = threadIdx.x;
    int tr   = tid >> 4;   // 0..15
    int tc   = tid & 15;   // 0..15

    float acc[4][8];
#pragma unroll
    for (int i = 0; i < 4; i++)
#pragma unroll
        for (int j = 0; j < 8; j++) acc[i][j] = 0.f;

    for (int k0 = 0; k0 < Ktot; k0 += 128) {
        // load A tile: 64x128 = 2048 float4
#pragma unroll
        for (int i = 0; i < 8; i++) {
            int idx = tid + i * 256;
            int r = idx >> 5;
            int c = (idx & 31) << 2;
            float4 val;
            if (row0 + r < M)
                val = *(const float4*)&A[(size_t)(row0 + r) * lda + k0 + c];
            else
                val = make_float4(0.f, 0.f, 0.f, 0.f);
            *(float4*)&As[r * 128 + c] = val;
        }
        // load B tile: 128x128 = 4096 float4 (scalar stores into padded rows)
#pragma unroll
        for (int i = 0; i < 16; i++) {
            int idx = tid + i * 256;
            int r = idx >> 5;
            int c = (idx & 31) << 2;
            float4 val = *(const float4*)&B[(size_t)(k0 + r) * ldb + col0 + c];
            float* d = &Bs[r * BNP + c];
            d[0] = val.x; d[1] = val.y; d[2] = val.z; d[3] = val.w;
        }
        __syncthreads();

#pragma unroll 4
        for (int k = 0; k < 128; k++) {
            float a[4], bb[8];
#pragma unroll
            for (int i = 0; i < 4; i++) a[i] = As[(tr * 4 + i) * 128 + k];
#pragma unroll
            for (int j = 0; j < 8; j++) bb[j] = Bs[k * BNP + tc + 16 * j];
#pragma unroll
            for (int i = 0; i < 4; i++)
#pragma unroll
                for (int j = 0; j < 8; j++) acc[i][j] += a[i] * bb[j];
        }
        __syncthreads();
    }

#pragma unroll
    for (int i = 0; i < 4; i++) {
        int r = row0 + tr * 4 + i;
        if (r >= M) break;
#pragma unroll
        for (int j = 0; j < 8; j++) {
            int c = col0 + tc + 16 * j;
            float val = acc[i][j] + bias[c];
            if (RELU) val = fmaxf(val, 0.f);
            if (RESID) val += resid[(size_t)r * ldo + c];
            out[(size_t)r * ldo + c] = val;
        }
    }
}

// ---------------- launch ----------------------------------------------------
extern "C" void kernel_launch(void* const* d_in, const int* in_sizes, int n_in,
                              void* d_out, int out_size) {
    const float* x     = (const float*)d_in[0];
    const int*   ei    = (const int*)d_in[1];
    const float* Wq    = (const float*)d_in[2];
    const float* bq    = (const float*)d_in[3];
    const float* Wk    = (const float*)d_in[4];
    const float* bk    = (const float*)d_in[5];
    const float* Wv    = (const float*)d_in[6];
    const float* bv    = (const float*)d_in[7];
    const float* Wo    = (const float*)d_in[8];
    const float* bo    = (const float*)d_in[9];
    const float* W1    = (const float*)d_in[10];
    const float* b1    = (const float*)d_in[11];
    const float* W2    = (const float*)d_in[12];
    const float* b2    = (const float*)d_in[13];
    const float* g1    = (const float*)d_in[14];
    const float* beta1 = (const float*)d_in[15];
    const float* g2    = (const float*)d_in[16];
    const float* beta2 = (const float*)d_in[17];
    float*       out   = (float*)d_out;

    float *h, *Q, *K, *V, *aggr, *x2, *hidden;
    cudaGetSymbolAddress((void**)&h,      g_h);
    cudaGetSymbolAddress((void**)&Q,      g_Q);
    cudaGetSymbolAddress((void**)&K,      g_K);
    cudaGetSymbolAddress((void**)&V,      g_V);
    cudaGetSymbolAddress((void**)&aggr,   g_aggr);
    cudaGetSymbolAddress((void**)&x2,     g_x2);
    cudaGetSymbolAddress((void**)&hidden, g_hidden);

    const size_t smem = (64 * 128 + 128 * 132) * sizeof(float);  // 100352 B
    cudaFuncSetAttribute(gemm_kernel<false, false>,
                         cudaFuncAttributeMaxDynamicSharedMemorySize, (int)smem);
    cudaFuncSetAttribute(gemm_kernel<false, true>,
                         cudaFuncAttributeMaxDynamicSharedMemorySize, (int)smem);
    cudaFuncSetAttribute(gemm_kernel<true, false>,
                         cudaFuncAttributeMaxDynamicSharedMemorySize, (int)smem);

    const int gemm_gx = (NN + 63) / 64;  // 1563

    // 1) h = LN(x) * g1 + beta1
    ln_kernel<<<(NN + 7) / 8, 256>>>(x, g1, beta1, h);

    // 2) Q,K,V = h @ W{q,k,v} + b
    gemm_kernel<false, false><<<dim3(gemm_gx, 1), 256, smem>>>(
        h, CC, Wq, CC, bq, nullptr, Q, CC, NN, CC);
    gemm_kernel<false, false><<<dim3(gemm_gx, 1), 256, smem>>>(
        h, CC, Wk, CC, bk, nullptr, K, CC, NN, CC);
    gemm_kernel<false, false><<<dim3(gemm_gx, 1), 256, smem>>>(
        h, CC, Wv, CC, bv, nullptr, V, CC, NN, CC);

    // 3) aggr = 0; scatter edge messages
    zero_kernel<<<2048, 256>>>((float4*)aggr, (size_t)NN * CC / 4);
    edge_kernel<<<(EE * 32 + 255) / 256, 256>>>(ei, Q, K, V, aggr);

    // 4) x2 = aggr @ Wo + bo + x
    gemm_kernel<false, true><<<dim3(gemm_gx, 1), 256, smem>>>(
        aggr, CC, Wo, CC, bo, x, x2, CC, NN, CC);

    // 5) h = LN(x2) * g2 + beta2
    ln_kernel<<<(NN + 7) / 8, 256>>>(x2, g2, beta2, h);

    // 6) hidden = relu(h @ W1 + b1)   [N,128]@[128,512]
    gemm_kernel<true, false><<<dim3(gemm_gx, 4), 256, smem>>>(
        h, CC, W1, HIDDEN, b1, nullptr, hidden, HIDDEN, NN, CC);

    // 7) out = hidden @ W2 + b2 + x2  [N,512]@[512,128]
    gemm_kernel<false, true><<<dim3(gemm_gx, 1), 256, smem>>>(
        hidden, HIDDEN, W2, CC, b2, x2, out, CC, NN, HIDDEN);
}

// round 3
// speedup vs baseline: 1.7907x; 1.7907x over previous
#include <cuda_runtime.h>

#define NN 100000
#define CC 128
#define EE 600000
#define HIDDEN 512

// ---------------- scratch (device globals; no allocations allowed) ----------
__device__ float g_h[(size_t)NN * CC];
__device__ float g_Q[(size_t)NN * CC];
__device__ float g_K[(size_t)NN * CC];
__device__ float g_V[(size_t)NN * CC];
__device__ float g_aggr[(size_t)NN * CC];
__device__ float g_x2[(size_t)NN * CC];
__device__ float g_hidden[(size_t)NN * HIDDEN];

// ---------------- LayerNorm: one warp per row (C=128 -> float4/lane) --------
__global__ void ln_kernel(const float* __restrict__ x,
                          const float* __restrict__ g,
                          const float* __restrict__ b,
                          float* __restrict__ out) {
    int row  = blockIdx.x * 8 + (threadIdx.x >> 5);
    int lane = threadIdx.x & 31;
    if (row >= NN) return;
    float4 v = *(const float4*)&x[(size_t)row * CC + lane * 4];
    float s  = v.x + v.y + v.z + v.w;
    float ss = v.x * v.x + v.y * v.y + v.z * v.z + v.w * v.w;
#pragma unroll
    for (int d = 16; d; d >>= 1) {
        s  += __shfl_xor_sync(0xffffffffu, s, d);
        ss += __shfl_xor_sync(0xffffffffu, ss, d);
    }
    float mu  = s * (1.0f / CC);
    float var = ss * (1.0f / CC) - mu * mu;
    float inv = rsqrtf(var + 1e-5f);
    float4 gg = *(const float4*)&g[lane * 4];
    float4 bb = *(const float4*)&b[lane * 4];
    float4 o;
    o.x = (v.x - mu) * inv * gg.x + bb.x;
    o.y = (v.y - mu) * inv * gg.y + bb.y;
    o.z = (v.z - mu) * inv * gg.z + bb.z;
    o.w = (v.w - mu) * inv * gg.w + bb.w;
    *(float4*)&out[(size_t)row * CC + lane * 4] = o;
}

// ---------------- zero-fill -------------------------------------------------
__global__ void zero_kernel(float4* __restrict__ p, size_t n4) {
    size_t i      = (size_t)blockIdx.x * blockDim.x + threadIdx.x;
    size_t stride = (size_t)gridDim.x * blockDim.x;
    float4 z = make_float4(0.f, 0.f, 0.f, 0.f);
    for (; i < n4; i += stride) p[i] = z;
}

// ---------------- per-edge attention: one warp per edge ---------------------
__global__ void edge_kernel(const int* __restrict__ ei,
                            const float* __restrict__ Q,
                            const float* __restrict__ K,
                            const float* __restrict__ V,
                            float* __restrict__ aggr) {
    int e    = (int)(((size_t)blockIdx.x * blockDim.x + threadIdx.x) >> 5);
    int lane = threadIdx.x & 31;
    if (e >= EE) return;
    int src = ei[e];
    int dst = ei[EE + e];

    float4 q = *(const float4*)&Q[(size_t)dst * CC + lane * 4];
    float4 k = *(const float4*)&K[(size_t)src * CC + lane * 4];
    float4 v = *(const float4*)&V[(size_t)src * CC + lane * 4];

    float p = q.x * k.x + q.y * k.y + q.z * k.z + q.w * k.w;
    p += __shfl_xor_sync(0xffffffffu, p, 1);
    p += __shfl_xor_sync(0xffffffffu, p, 2);
    float s = p * 0.25f;  // 1/sqrt(16)

    float m = s;
    m = fmaxf(m, __shfl_xor_sync(0xffffffffu, m, 4));
    m = fmaxf(m, __shfl_xor_sync(0xffffffffu, m, 8));
    m = fmaxf(m, __shfl_xor_sync(0xffffffffu, m, 16));
    float ex = __expf(s - m);
    float sum = ex;
    sum += __shfl_xor_sync(0xffffffffu, sum, 4);
    sum += __shfl_xor_sync(0xffffffffu, sum, 8);
    sum += __shfl_xor_sync(0xffffffffu, sum, 16);
    float a = ex / sum;

    float* base = &aggr[(size_t)dst * CC + lane * 4];
    atomicAdd(base + 0, v.x * a);
    atomicAdd(base + 1, v.y * a);
    atomicAdd(base + 2, v.z * a);
    atomicAdd(base + 3, v.w * a);
}

// ---------------- TF32 tensor-core GEMM ------------------------------------
// out[M,N] = act(A[M,K] @ B[K,N] + bias) [+ resid]
// BM=128, BN=128, BK=32; 256 threads = 8 warps (4 m x 2 n), warp tile 32x64.
// mma.sync.m16n8k8 tf32: 2 m-frags x 8 n-frags per warp.
// Double-buffered smem, register-staged LDG; cvt.rna.tf32 on store-to-smem.
// Padding AP=36 / BP=136 -> all fragment LDS patterns conflict-free.

__device__ __forceinline__ unsigned f2tf(float f) {
    unsigned u;
    asm("cvt.rna.tf32.f32 %0, %1;" : "=r"(u) : "f"(f));
    return u;
}

#define AP 36
#define BP 136

template <bool RELU, bool RESID>
__global__ void __launch_bounds__(256)
gemm_tf32(const float* __restrict__ A, int lda,
          const float* __restrict__ B, int ldb,
          const float* __restrict__ bias,
          const float* __restrict__ resid,
          float* __restrict__ out, int ldo,
          int M, int Ktot) {
    extern __shared__ unsigned smem_u[];
    unsigned* As = smem_u;                 // [2][128*AP]
    unsigned* Bs = smem_u + 2 * 128 * AP;  // [2][32*BP]

    const int tid  = threadIdx.x;
    const int lane = tid & 31;
    const int wid  = tid >> 5;
    const int wr0  = (wid & 3) * 32;   // warp row within tile
    const int wc0  = (wid >> 2) * 64;  // warp col within tile
    const int gid  = lane >> 2;        // 0..7
    const int tig  = lane & 3;         // 0..3
    const int row0 = blockIdx.x * 128;
    const int col0 = blockIdx.y * 128;

    // global-load coordinates
    const int ar  = tid >> 3;          // 0..31 (A rows, 4 passes of 32)
    const int ac  = (tid & 7) * 4;     // A col (float4)
    const int brr = tid >> 5;          // 0..7  (B rows, 4 passes of 8)
    const int bcc = (tid & 31) * 4;    // B col (float4)

    float acc[2][8][4];
#pragma unroll
    for (int mt = 0; mt < 2; mt++)
#pragma unroll
        for (int nt = 0; nt < 8; nt++)
#pragma unroll
            for (int i = 0; i < 4; i++) acc[mt][nt][i] = 0.f;

    float4 a_reg[4], b_reg[4];

    auto ldg = [&](int k0) {
#pragma unroll
        for (int p = 0; p < 4; p++) {
            int r = ar + p * 32;
            a_reg[p] = (row0 + r < M)
                           ? *(const float4*)&A[(size_t)(row0 + r) * lda + k0 + ac]
                           : make_float4(0.f, 0.f, 0.f, 0.f);
        }
#pragma unroll
        for (int p = 0; p < 4; p++) {
            int r = brr + p * 8;
            b_reg[p] = *(const float4*)&B[(size_t)(k0 + r) * ldb + col0 + bcc];
        }
    };

    auto sts = [&](int buf) {
        unsigned* as = As + buf * 128 * AP;
        unsigned* bs = Bs + buf * 32 * BP;
#pragma unroll
        for (int p = 0; p < 4; p++) {
            int r = ar + p * 32;
            uint4 u;
            u.x = f2tf(a_reg[p].x); u.y = f2tf(a_reg[p].y);
            u.z = f2tf(a_reg[p].z); u.w = f2tf(a_reg[p].w);
            *(uint4*)&as[r * AP + ac] = u;
        }
#pragma unroll
        for (int p = 0; p < 4; p++) {
            int r = brr + p * 8;
            uint4 u;
            u.x = f2tf(b_reg[p].x); u.y = f2tf(b_reg[p].y);
            u.z = f2tf(b_reg[p].z); u.w = f2tf(b_reg[p].w);
            *(uint4*)&bs[r * BP + bcc] = u;
        }
    };

    ldg(0);
    sts(0);
    __syncthreads();

    const int KT = Ktot >> 5;
    for (int kt = 0; kt < KT; kt++) {
        const int buf = kt & 1;
        if (kt + 1 < KT) ldg((kt + 1) * 32);  // hide LDG behind mma

        const unsigned* as = As + buf * 128 * AP;
        const unsigned* bs = Bs + buf * 32 * BP;

#pragma unroll
        for (int ks = 0; ks < 4; ks++) {
            unsigned afr[2][4];
#pragma unroll
            for (int mt = 0; mt < 2; mt++) {
                int rb = wr0 + mt * 16;
                int kc = ks * 8 + tig;
                afr[mt][0] = as[(rb + gid) * AP + kc];
                afr[mt][1] = as[(rb + gid + 8) * AP + kc];
                afr[mt][2] = as[(rb + gid) * AP + kc + 4];
                afr[mt][3] = as[(rb + gid + 8) * AP + kc + 4];
            }
#pragma unroll
            for (int nt = 0; nt < 8; nt++) {
                unsigned bfr[2];
                int cb = wc0 + nt * 8 + gid;
                bfr[0] = bs[(ks * 8 + tig) * BP + cb];
                bfr[1] = bs[(ks * 8 + tig + 4) * BP + cb];
#pragma unroll
                for (int mt = 0; mt < 2; mt++) {
                    asm volatile(
                        "mma.sync.aligned.m16n8k8.row.col.f32.tf32.tf32.f32 "
                        "{%0,%1,%2,%3}, {%4,%5,%6,%7}, {%8,%9}, {%0,%1,%2,%3};"
                        : "+f"(acc[mt][nt][0]), "+f"(acc[mt][nt][1]),
                          "+f"(acc[mt][nt][2]), "+f"(acc[mt][nt][3])
                        : "r"(afr[mt][0]), "r"(afr[mt][1]),
                          "r"(afr[mt][2]), "r"(afr[mt][3]),
                          "r"(bfr[0]), "r"(bfr[1]));
                }
            }
        }

        if (kt + 1 < KT) sts(buf ^ 1);
        __syncthreads();
    }

    // ---------------- epilogue ----------------
#pragma unroll
    for (int mt = 0; mt < 2; mt++) {
        int r0 = row0 + wr0 + mt * 16 + gid;
#pragma unroll
        for (int nt = 0; nt < 8; nt++) {
            int col = col0 + wc0 + nt * 8 + 2 * tig;
            float b0 = bias[col], b1 = bias[col + 1];
            float v0 = acc[mt][nt][0] + b0;
            float v1 = acc[mt][nt][1] + b1;
            float v2 = acc[mt][nt][2] + b0;
            float v3 = acc[mt][nt][3] + b1;
            if (RELU) {
                v0 = fmaxf(v0, 0.f); v1 = fmaxf(v1, 0.f);
                v2 = fmaxf(v2, 0.f); v3 = fmaxf(v3, 0.f);
            }
            if (r0 < M) {
                if (RESID) {
                    v0 += resid[(size_t)r0 * ldo + col];
                    v1 += resid[(size_t)r0 * ldo + col + 1];
                }
                float2 o; o.x = v0; o.y = v1;
                *(float2*)&out[(size_t)r0 * ldo + col] = o;
            }
            if (r0 + 8 < M) {
                if (RESID) {
                    v2 += resid[(size_t)(r0 + 8) * ldo + col];
                    v3 += resid[(size_t)(r0 + 8) * ldo + col + 1];
                }
                float2 o; o.x = v2; o.y = v3;
                *(float2*)&out[(size_t)(r0 + 8) * ldo + col] = o;
            }
        }
    }
}

// ---------------- launch ----------------------------------------------------
extern "C" void kernel_launch(void* const* d_in, const int* in_sizes, int n_in,
                              void* d_out, int out_size) {
    const float* x     = (const float*)d_in[0];
    const int*   ei    = (const int*)d_in[1];
    const float* Wq    = (const float*)d_in[2];
    const float* bq    = (const float*)d_in[3];
    const float* Wk    = (const float*)d_in[4];
    const float* bk    = (const float*)d_in[5];
    const float* Wv    = (const float*)d_in[6];
    const float* bv    = (const float*)d_in[7];
    const float* Wo    = (const float*)d_in[8];
    const float* bo    = (const float*)d_in[9];
    const float* W1    = (const float*)d_in[10];
    const float* b1    = (const float*)d_in[11];
    const float* W2    = (const float*)d_in[12];
    const float* b2    = (const float*)d_in[13];
    const float* g1    = (const float*)d_in[14];
    const float* beta1 = (const float*)d_in[15];
    const float* g2    = (const float*)d_in[16];
    const float* beta2 = (const float*)d_in[17];
    float*       out   = (float*)d_out;

    float *h, *Q, *K, *V, *aggr, *x2, *hidden;
    cudaGetSymbolAddress((void**)&h,      g_h);
    cudaGetSymbolAddress((void**)&Q,      g_Q);
    cudaGetSymbolAddress((void**)&K,      g_K);
    cudaGetSymbolAddress((void**)&V,      g_V);
    cudaGetSymbolAddress((void**)&aggr,   g_aggr);
    cudaGetSymbolAddress((void**)&x2,     g_x2);
    cudaGetSymbolAddress((void**)&hidden, g_hidden);

    const size_t smem = (2 * 128 * AP + 2 * 32 * BP) * sizeof(unsigned);  // 71680
    cudaFuncSetAttribute(gemm_tf32<false, false>,
                         cudaFuncAttributeMaxDynamicSharedMemorySize, (int)smem);
    cudaFuncSetAttribute(gemm_tf32<false, true>,
                         cudaFuncAttributeMaxDynamicSharedMemorySize, (int)smem);
    cudaFuncSetAttribute(gemm_tf32<true, false>,
                         cudaFuncAttributeMaxDynamicSharedMemorySize, (int)smem);

    const int gx = (NN + 127) / 128;  // 782

    // 1) h = LN(x)
    ln_kernel<<<(NN + 7) / 8, 256>>>(x, g1, beta1, h);

    // 2) Q,K,V = h @ W{q,k,v} + b
    gemm_tf32<false, false><<<dim3(gx, 1), 256, smem>>>(
        h, CC, Wq, CC, bq, nullptr, Q, CC, NN, CC);
    gemm_tf32<false, false><<<dim3(gx, 1), 256, smem>>>(
        h, CC, Wk, CC, bk, nullptr, K, CC, NN, CC);
    gemm_tf32<false, false><<<dim3(gx, 1), 256, smem>>>(
        h, CC, Wv, CC, bv, nullptr, V, CC, NN, CC);

    // 3) aggr = 0; scatter edge messages
    zero_kernel<<<2048, 256>>>((float4*)aggr, (size_t)NN * CC / 4);
    edge_kernel<<<(EE * 32 + 255) / 256, 256>>>(ei, Q, K, V, aggr);

    // 4) x2 = aggr @ Wo + bo + x
    gemm_tf32<false, true><<<dim3(gx, 1), 256, smem>>>(
        aggr, CC, Wo, CC, bo, x, x2, CC, NN, CC);

    // 5) h = LN(x2)
    ln_kernel<<<(NN + 7) / 8, 256>>>(x2, g2, beta2, h);

    // 6) hidden = relu(h @ W1 + b1)
    gemm_tf32<true, false><<<dim3(gx, 4), 256, smem>>>(
        h, CC, W1, HIDDEN, b1, nullptr, hidden, HIDDEN, NN, CC);

    // 7) out = hidden @ W2 + b2 + x2
    gemm_tf32<false, true><<<dim3(gx, 1), 256, smem>>>(
        hidden, HIDDEN, W2, CC, b2, x2, out, CC, NN, HIDDEN);
}

// round 4
// speedup vs baseline: 2.1587x; 1.2055x over previous
#include <cuda_runtime.h>

#define NN 100000
#define CC 128
#define EE 600000
#define HIDDEN 512

// ---------------- scratch (device globals; no allocations allowed) ----------
__device__ float g_h[(size_t)NN * CC];
__device__ float g_Q[(size_t)NN * CC];
__device__ float g_K[(size_t)NN * CC];
__device__ float g_V[(size_t)NN * CC];
__device__ float g_aggr[(size_t)NN * CC];
__device__ float g_x2[(size_t)NN * CC];
__device__ float g_hidden[(size_t)NN * HIDDEN];

// ---------------- LayerNorm: one warp per row (C=128 -> float4/lane) --------
__global__ void ln_kernel(const float* __restrict__ x,
                          const float* __restrict__ g,
                          const float* __restrict__ b,
                          float* __restrict__ out) {
    int row  = blockIdx.x * 8 + (threadIdx.x >> 5);
    int lane = threadIdx.x & 31;
    if (row >= NN) return;
    float4 v = *(const float4*)&x[(size_t)row * CC + lane * 4];
    float s  = v.x + v.y + v.z + v.w;
    float ss = v.x * v.x + v.y * v.y + v.z * v.z + v.w * v.w;
#pragma unroll
    for (int d = 16; d; d >>= 1) {
        s  += __shfl_xor_sync(0xffffffffu, s, d);
        ss += __shfl_xor_sync(0xffffffffu, ss, d);
    }
    float mu  = s * (1.0f / CC);
    float var = ss * (1.0f / CC) - mu * mu;
    float inv = rsqrtf(var + 1e-5f);
    float4 gg = *(const float4*)&g[lane * 4];
    float4 bb = *(const float4*)&b[lane * 4];
    float4 o;
    o.x = (v.x - mu) * inv * gg.x + bb.x;
    o.y = (v.y - mu) * inv * gg.y + bb.y;
    o.z = (v.z - mu) * inv * gg.z + bb.z;
    o.w = (v.w - mu) * inv * gg.w + bb.w;
    *(float4*)&out[(size_t)row * CC + lane * 4] = o;
}

// ---------------- zero-fill -------------------------------------------------
__global__ void zero_kernel(float4* __restrict__ p, size_t n4) {
    size_t i      = (size_t)blockIdx.x * blockDim.x + threadIdx.x;
    size_t stride = (size_t)gridDim.x * blockDim.x;
    float4 z = make_float4(0.f, 0.f, 0.f, 0.f);
    for (; i < n4; i += stride) p[i] = z;
}

// ---------------- per-edge attention: one warp per edge ---------------------
__global__ void edge_kernel(const int* __restrict__ ei,
                            const float* __restrict__ Q,
                            const float* __restrict__ K,
                            const float* __restrict__ V,
                            float* __restrict__ aggr) {
    int e    = (int)(((size_t)blockIdx.x * blockDim.x + threadIdx.x) >> 5);
    int lane = threadIdx.x & 31;
    if (e >= EE) return;
    int src = ei[e];
    int dst = ei[EE + e];

    float4 q = *(const float4*)&Q[(size_t)dst * CC + lane * 4];
    float4 k = *(const float4*)&K[(size_t)src * CC + lane * 4];
    float4 v = *(const float4*)&V[(size_t)src * CC + lane * 4];

    float p = q.x * k.x + q.y * k.y + q.z * k.z + q.w * k.w;
    p += __shfl_xor_sync(0xffffffffu, p, 1);
    p += __shfl_xor_sync(0xffffffffu, p, 2);
    float s = p * 0.25f;  // 1/sqrt(16)

    float m = s;
    m = fmaxf(m, __shfl_xor_sync(0xffffffffu, m, 4));
    m = fmaxf(m, __shfl_xor_sync(0xffffffffu, m, 8));
    m = fmaxf(m, __shfl_xor_sync(0xffffffffu, m, 16));
    float ex = __expf(s - m);
    float sum = ex;
    sum += __shfl_xor_sync(0xffffffffu, sum, 4);
    sum += __shfl_xor_sync(0xffffffffu, sum, 8);
    sum += __shfl_xor_sync(0xffffffffu, sum, 16);
    float a = ex / sum;

    float* base = &aggr[(size_t)dst * CC + lane * 4];
    atomicAdd(base + 0, v.x * a);
    atomicAdd(base + 1, v.y * a);
    atomicAdd(base + 2, v.z * a);
    atomicAdd(base + 3, v.w * a);
}

// ---------------- TF32 tensor-core GEMM body --------------------------------
// out[M,N] = act(A[M,K] @ B[K,N] + bias) [+ resid]
// BM=128, BN=128, BK=32; 256 threads = 8 warps (4 m x 2 n), warp tile 32x64.
// mma.sync.m16n8k8 tf32, double-buffered smem, register-staged LDG with
// cvt.rna.tf32 at STS. Padding AP=36 / BP=136 -> conflict-free fragment LDS.

__device__ __forceinline__ unsigned f2tf(float f) {
    unsigned u;
    asm("cvt.rna.tf32.f32 %0, %1;" : "=r"(u) : "f"(f));
    return u;
}

#define AP 36
#define BP 136
#define GEMM_SMEM ((2 * 128 * AP + 2 * 32 * BP) * 4)

template <bool RELU, bool RESID>
__device__ __forceinline__ void gemm_body(
    const float* __restrict__ A, int lda,
    const float* __restrict__ B, int ldb,
    const float* __restrict__ bias,
    const float* __restrict__ resid,
    float* __restrict__ out, int ldo,
    int M, int Ktot, int row0, int col0, unsigned* smem_u) {
    unsigned* As = smem_u;                 // [2][128*AP]
    unsigned* Bs = smem_u + 2 * 128 * AP;  // [2][32*BP]

    const int tid  = threadIdx.x;
    const int lane = tid & 31;
    const int wid  = tid >> 5;
    const int wr0  = (wid & 3) * 32;   // warp row within tile
    const int wc0  = (wid >> 2) * 64;  // warp col within tile
    const int gid  = lane >> 2;        // 0..7
    const int tig  = lane & 3;         // 0..3

    // global-load coordinates
    const int ar  = tid >> 3;          // 0..31 (A rows, 4 passes of 32)
    const int ac  = (tid & 7) * 4;     // A col (float4)
    const int brr = tid >> 5;          // 0..7  (B rows, 4 passes of 8)
    const int bcc = (tid & 31) * 4;    // B col (float4)

    float acc[2][8][4];
#pragma unroll
    for (int mt = 0; mt < 2; mt++)
#pragma unroll
        for (int nt = 0; nt < 8; nt++)
#pragma unroll
            for (int i = 0; i < 4; i++) acc[mt][nt][i] = 0.f;

    float4 a_reg[4], b_reg[4];

    auto ldg = [&](int k0) {
#pragma unroll
        for (int p = 0; p < 4; p++) {
            int r = ar + p * 32;
            a_reg[p] = (row0 + r < M)
                           ? *(const float4*)&A[(size_t)(row0 + r) * lda + k0 + ac]
                           : make_float4(0.f, 0.f, 0.f, 0.f);
        }
#pragma unroll
        for (int p = 0; p < 4; p++) {
            int r = brr + p * 8;
            b_reg[p] = *(const float4*)&B[(size_t)(k0 + r) * ldb + col0 + bcc];
        }
    };

    auto sts = [&](int buf) {
        unsigned* as = As + buf * 128 * AP;
        unsigned* bs = Bs + buf * 32 * BP;
#pragma unroll
        for (int p = 0; p < 4; p++) {
            int r = ar + p * 32;
            uint4 u;
            u.x = f2tf(a_reg[p].x); u.y = f2tf(a_reg[p].y);
            u.z = f2tf(a_reg[p].z); u.w = f2tf(a_reg[p].w);
            *(uint4*)&as[r * AP + ac] = u;
        }
#pragma unroll
        for (int p = 0; p < 4; p++) {
            int r = brr + p * 8;
            uint4 u;
            u.x = f2tf(b_reg[p].x); u.y = f2tf(b_reg[p].y);
            u.z = f2tf(b_reg[p].z); u.w = f2tf(b_reg[p].w);
            *(uint4*)&bs[r * BP + bcc] = u;
        }
    };

    ldg(0);
    sts(0);
    __syncthreads();

    const int KT = Ktot >> 5;
    for (int kt = 0; kt < KT; kt++) {
        const int buf = kt & 1;
        if (kt + 1 < KT) ldg((kt + 1) * 32);  // hide LDG behind mma

        const unsigned* as = As + buf * 128 * AP;
        const unsigned* bs = Bs + buf * 32 * BP;

#pragma unroll
        for (int ks = 0; ks < 4; ks++) {
            unsigned afr[2][4];
#pragma unroll
            for (int mt = 0; mt < 2; mt++) {
                int rb = wr0 + mt * 16;
                int kc = ks * 8 + tig;
                afr[mt][0] = as[(rb + gid) * AP + kc];
                afr[mt][1] = as[(rb + gid + 8) * AP + kc];
                afr[mt][2] = as[(rb + gid) * AP + kc + 4];
                afr[mt][3] = as[(rb + gid + 8) * AP + kc + 4];
            }
#pragma unroll
            for (int nt = 0; nt < 8; nt++) {
                unsigned bfr[2];
                int cb = wc0 + nt * 8 + gid;
                bfr[0] = bs[(ks * 8 + tig) * BP + cb];
                bfr[1] = bs[(ks * 8 + tig + 4) * BP + cb];
#pragma unroll
                for (int mt = 0; mt < 2; mt++) {
                    asm volatile(
                        "mma.sync.aligned.m16n8k8.row.col.f32.tf32.tf32.f32 "
                        "{%0,%1,%2,%3}, {%4,%5,%6,%7}, {%8,%9}, {%0,%1,%2,%3};"
                        : "+f"(acc[mt][nt][0]), "+f"(acc[mt][nt][1]),
                          "+f"(acc[mt][nt][2]), "+f"(acc[mt][nt][3])
                        : "r"(afr[mt][0]), "r"(afr[mt][1]),
                          "r"(afr[mt][2]), "r"(afr[mt][3]),
                          "r"(bfr[0]), "r"(bfr[1]));
                }
            }
        }

        if (kt + 1 < KT) sts(buf ^ 1);
        __syncthreads();
    }

    // ---------------- epilogue ----------------
#pragma unroll
    for (int mt = 0; mt < 2; mt++) {
        int r0 = row0 + wr0 + mt * 16 + gid;
#pragma unroll
        for (int nt = 0; nt < 8; nt++) {
            int col = col0 + wc0 + nt * 8 + 2 * tig;
            float b0 = bias[col], b1 = bias[col + 1];
            float v0 = acc[mt][nt][0] + b0;
            float v1 = acc[mt][nt][1] + b1;
            float v2 = acc[mt][nt][2] + b0;
            float v3 = acc[mt][nt][3] + b1;
            if (RELU) {
                v0 = fmaxf(v0, 0.f); v1 = fmaxf(v1, 0.f);
                v2 = fmaxf(v2, 0.f); v3 = fmaxf(v3, 0.f);
            }
            if (r0 < M) {
                if (RESID) {
                    v0 += resid[(size_t)r0 * ldo + col];
                    v1 += resid[(size_t)r0 * ldo + col + 1];
                }
                float2 o; o.x = v0; o.y = v1;
                *(float2*)&out[(size_t)r0 * ldo + col] = o;
            }
            if (r0 + 8 < M) {
                if (RESID) {
                    v2 += resid[(size_t)(r0 + 8) * ldo + col];
                    v3 += resid[(size_t)(r0 + 8) * ldo + col + 1];
                }
                float2 o; o.x = v2; o.y = v3;
                *(float2*)&out[(size_t)(r0 + 8) * ldo + col] = o;
            }
        }
    }
}

template <bool RELU, bool RESID>
__global__ void __launch_bounds__(256, 2)
gemm_tf32(const float* __restrict__ A, int lda,
          const float* __restrict__ B, int ldb,
          const float* __restrict__ bias,
          const float* __restrict__ resid,
          float* __restrict__ out, int ldo,
          int M, int Ktot) {
    extern __shared__ unsigned smem_u[];
    gemm_body<RELU, RESID>(A, lda, B, ldb, bias, resid, out, ldo, M, Ktot,
                           blockIdx.x * 128, blockIdx.y * 128, smem_u);
}

// fused QKV: grid.y in {0,1,2} selects the weight/bias/output triple
__global__ void __launch_bounds__(256, 2)
qkv_tf32(const float* __restrict__ h,
         const float* __restrict__ Wq, const float* __restrict__ bq,
         const float* __restrict__ Wk, const float* __restrict__ bk,
         const float* __restrict__ Wv, const float* __restrict__ bv,
         float* __restrict__ Q, float* __restrict__ K, float* __restrict__ V) {
    extern __shared__ unsigned smem_u[];
    const float* B;
    const float* bias;
    float* out;
    if (blockIdx.y == 0)      { B = Wq; bias = bq; out = Q; }
    else if (blockIdx.y == 1) { B = Wk; bias = bk; out = K; }
    else                      { B = Wv; bias = bv; out = V; }
    gemm_body<false, false>(h, CC, B, CC, bias, nullptr, out, CC, NN, CC,
                            blockIdx.x * 128, 0, smem_u);
}

// ---------------- launch ----------------------------------------------------
extern "C" void kernel_launch(void* const* d_in, const int* in_sizes, int n_in,
                              void* d_out, int out_size) {
    const float* x     = (const float*)d_in[0];
    const int*   ei    = (const int*)d_in[1];
    const float* Wq    = (const float*)d_in[2];
    const float* bq    = (const float*)d_in[3];
    const float* Wk    = (const float*)d_in[4];
    const float* bk    = (const float*)d_in[5];
    const float* Wv    = (const float*)d_in[6];
    const float* bv    = (const float*)d_in[7];
    const float* Wo    = (const float*)d_in[8];
    const float* bo    = (const float*)d_in[9];
    const float* W1    = (const float*)d_in[10];
    const float* b1    = (const float*)d_in[11];
    const float* W2    = (const float*)d_in[12];
    const float* b2    = (const float*)d_in[13];
    const float* g1    = (const float*)d_in[14];
    const float* beta1 = (const float*)d_in[15];
    const float* g2    = (const float*)d_in[16];
    const float* beta2 = (const float*)d_in[17];
    float*       out   = (float*)d_out;

    float *h, *Q, *K, *V, *aggr, *x2, *hidden;
    cudaGetSymbolAddress((void**)&h,      g_h);
    cudaGetSymbolAddress((void**)&Q,      g_Q);
    cudaGetSymbolAddress((void**)&K,      g_K);
    cudaGetSymbolAddress((void**)&V,      g_V);
    cudaGetSymbolAddress((void**)&aggr,   g_aggr);
    cudaGetSymbolAddress((void**)&x2,     g_x2);
    cudaGetSymbolAddress((void**)&hidden, g_hidden);

    const int smem = GEMM_SMEM;  // 71680 B
    cudaFuncSetAttribute(gemm_tf32<false, true>,
                         cudaFuncAttributeMaxDynamicSharedMemorySize, smem);
    cudaFuncSetAttribute(gemm_tf32<true, false>,
                         cudaFuncAttributeMaxDynamicSharedMemorySize, smem);
    cudaFuncSetAttribute(qkv_tf32,
                         cudaFuncAttributeMaxDynamicSharedMemorySize, smem);

    const int gx = (NN + 127) / 128;  // 782

    // 1) h = LN(x)
    ln_kernel<<<(NN + 7) / 8, 256>>>(x, g1, beta1, h);

    // 2) Q,K,V = h @ W{q,k,v} + b  (single fused launch)
    qkv_tf32<<<dim3(gx, 3), 256, smem>>>(h, Wq, bq, Wk, bk, Wv, bv, Q, K, V);

    // 3) aggr = 0; scatter edge messages
    zero_kernel<<<2048, 256>>>((float4*)aggr, (size_t)NN * CC / 4);
    edge_kernel<<<(EE * 32 + 255) / 256, 256>>>(ei, Q, K, V, aggr);

    // 4) x2 = aggr @ Wo + bo + x
    gemm_tf32<false, true><<<dim3(gx, 1), 256, smem>>>(
        aggr, CC, Wo, CC, bo, x, x2, CC, NN, CC);

    // 5) h = LN(x2)
    ln_kernel<<<(NN + 7) / 8, 256>>>(x2, g2, beta2, h);

    // 6) hidden = relu(h @ W1 + b1)
    gemm_tf32<true, false><<<dim3(gx, 4), 256, smem>>>(
        h, CC, W1, HIDDEN, b1, nullptr, hidden, HIDDEN, NN, CC);

    // 7) out = hidden @ W2 + b2 + x2
    gemm_tf32<false, true><<<dim3(gx, 1), 256, smem>>>(
        hidden, HIDDEN, W2, CC, b2, x2, out, CC, NN, HIDDEN);
}

// round 5
// speedup vs baseline: 2.3398x; 1.0839x over previous
#include <cuda_runtime.h>

#define NN 100000
#define CC 128
#define EE 600000
#define HIDDEN 512

// ---------------- scratch (device globals; no allocations allowed) ----------
__device__ float g_h[(size_t)NN * CC];
__device__ float g_Q[(size_t)NN * CC];
__device__ float g_K[(size_t)NN * CC];
__device__ float g_V[(size_t)NN * CC];
__device__ float g_aggr[(size_t)NN * CC];
__device__ float g_x2[(size_t)NN * CC];
__device__ float g_hidden[(size_t)NN * HIDDEN];
__device__ int   g_deg[NN];
__device__ int   g_off[NN + 1];
__device__ int   g_cursor[NN];
__device__ int   g_csr_src[EE];

// ---------------- LayerNorm: one warp per row -------------------------------
__global__ void ln_kernel(const float* __restrict__ x,
                          const float* __restrict__ g,
                          const float* __restrict__ b,
                          float* __restrict__ out) {
    int row  = blockIdx.x * 8 + (threadIdx.x >> 5);
    int lane = threadIdx.x & 31;
    if (row >= NN) return;
    float4 v = *(const float4*)&x[(size_t)row * CC + lane * 4];
    float s  = v.x + v.y + v.z + v.w;
    float ss = v.x * v.x + v.y * v.y + v.z * v.z + v.w * v.w;
#pragma unroll
    for (int d = 16; d; d >>= 1) {
        s  += __shfl_xor_sync(0xffffffffu, s, d);
        ss += __shfl_xor_sync(0xffffffffu, ss, d);
    }
    float mu  = s * (1.0f / CC);
    float var = ss * (1.0f / CC) - mu * mu;
    float inv = rsqrtf(var + 1e-5f);
    float4 gg = *(const float4*)&g[lane * 4];
    float4 bb = *(const float4*)&b[lane * 4];
    float4 o;
    o.x = (v.x - mu) * inv * gg.x + bb.x;
    o.y = (v.y - mu) * inv * gg.y + bb.y;
    o.z = (v.z - mu) * inv * gg.z + bb.z;
    o.w = (v.w - mu) * inv * gg.w + bb.w;
    *(float4*)&out[(size_t)row * CC + lane * 4] = o;
}

// ---------------- CSR build --------------------------------------------------
__global__ void zero_int_kernel(int* __restrict__ p, int n) {
    int i = blockIdx.x * blockDim.x + threadIdx.x;
    if (i < n) p[i] = 0;
}

__global__ void hist_kernel(const int* __restrict__ ei, int* __restrict__ deg) {
    int e = blockIdx.x * blockDim.x + threadIdx.x;
    if (e < EE) atomicAdd(&deg[ei[EE + e]], 1);
}

// single-block chunked exclusive scan over NN elements
__global__ void scan_kernel(const int* __restrict__ deg,
                            int* __restrict__ off,
                            int* __restrict__ cursor) {
    __shared__ int warp_sums[32];
    __shared__ int carry;
    int tid = threadIdx.x, lane = tid & 31, wid = tid >> 5;
    if (tid == 0) carry = 0;
    __syncthreads();
    for (int base = 0; base < NN; base += 1024) {
        int i = base + tid;
        int v = (i < NN) ? deg[i] : 0;
        int x = v;
#pragma unroll
        for (int d = 1; d < 32; d <<= 1) {
            int y = __shfl_up_sync(0xffffffffu, x, d);
            if (lane >= d) x += y;
        }
        if (lane == 31) warp_sums[wid] = x;
        __syncthreads();
        if (wid == 0) {
            int s = warp_sums[lane];
#pragma unroll
            for (int d = 1; d < 32; d <<= 1) {
                int y = __shfl_up_sync(0xffffffffu, s, d);
                if (lane >= d) s += y;
            }
            warp_sums[lane] = s;
        }
        __syncthreads();
        int woff = wid ? warp_sums[wid - 1] : 0;
        int excl = carry + woff + (x - v);
        if (i < NN) { off[i] = excl; cursor[i] = excl; }
        __syncthreads();
        if (tid == 0) carry += warp_sums[31];
        __syncthreads();
    }
    if (threadIdx.x == 0) off[NN] = carry;
}

__global__ void scatter_kernel(const int* __restrict__ ei,
                               int* __restrict__ cursor,
                               int* __restrict__ csr_src) {
    int e = blockIdx.x * blockDim.x + threadIdx.x;
    if (e >= EE) return;
    int dst = ei[EE + e];
    int pos = atomicAdd(&cursor[dst], 1);
    csr_src[pos] = ei[e];
}

// ---------------- aggregation: one warp per dst node ------------------------
// lane l covers channels [4l,4l+4); head = l/4 (HD=16 -> 4 lanes/head)
__global__ void aggr_kernel(const int* __restrict__ off,
                            const int* __restrict__ csr_src,
                            const float* __restrict__ Q,
                            const float* __restrict__ K,
                            const float* __restrict__ V,
                            float* __restrict__ aggr) {
    int n    = blockIdx.x * 8 + (threadIdx.x >> 5);
    int lane = threadIdx.x & 31;
    if (n >= NN) return;
    int s0 = off[n], s1 = off[n + 1];

    float4 q   = *(const float4*)&Q[(size_t)n * CC + lane * 4];
    float4 acc = make_float4(0.f, 0.f, 0.f, 0.f);

    for (int j = s0; j < s1; j++) {
        int src  = csr_src[j];  // uniform broadcast load
        float4 k = *(const float4*)&K[(size_t)src * CC + lane * 4];
        float4 v = *(const float4*)&V[(size_t)src * CC + lane * 4];

        float p = q.x * k.x + q.y * k.y + q.z * k.z + q.w * k.w;
        p += __shfl_xor_sync(0xffffffffu, p, 1);
        p += __shfl_xor_sync(0xffffffffu, p, 2);
        float s = p * 0.25f;  // 1/sqrt(16)

        float m = s;
        m = fmaxf(m, __shfl_xor_sync(0xffffffffu, m, 4));
        m = fmaxf(m, __shfl_xor_sync(0xffffffffu, m, 8));
        m = fmaxf(m, __shfl_xor_sync(0xffffffffu, m, 16));
        float ex  = __expf(s - m);
        float sum = ex;
        sum += __shfl_xor_sync(0xffffffffu, sum, 4);
        sum += __shfl_xor_sync(0xffffffffu, sum, 8);
        sum += __shfl_xor_sync(0xffffffffu, sum, 16);
        float a = ex / sum;

        acc.x += v.x * a;
        acc.y += v.y * a;
        acc.z += v.z * a;
        acc.w += v.w * a;
    }
    *(float4*)&aggr[(size_t)n * CC + lane * 4] = acc;
}

// ---------------- TF32 tensor-core GEMM body --------------------------------
__device__ __forceinline__ unsigned f2tf(float f) {
    unsigned u;
    asm("cvt.rna.tf32.f32 %0, %1;" : "=r"(u) : "f"(f));
    return u;
}

#define AP 36
#define BP 136
#define GEMM_SMEM ((2 * 128 * AP + 2 * 32 * BP) * 4)

template <bool RELU, bool RESID>
__device__ __forceinline__ void gemm_body(
    const float* __restrict__ A, int lda,
    const float* __restrict__ B, int ldb,
    const float* __restrict__ bias,
    const float* __restrict__ resid,
    float* __restrict__ out, int ldo,
    int M, int Ktot, int row0, int col0, unsigned* smem_u) {
    unsigned* As = smem_u;                 // [2][128*AP]
    unsigned* Bs = smem_u + 2 * 128 * AP;  // [2][32*BP]

    const int tid  = threadIdx.x;
    const int lane = tid & 31;
    const int wid  = tid >> 5;
    const int wr0  = (wid & 3) * 32;
    const int wc0  = (wid >> 2) * 64;
    const int gid  = lane >> 2;
    const int tig  = lane & 3;

    const int ar  = tid >> 3;
    const int ac  = (tid & 7) * 4;
    const int brr = tid >> 5;
    const int bcc = (tid & 31) * 4;

    float acc[2][8][4];
#pragma unroll
    for (int mt = 0; mt < 2; mt++)
#pragma unroll
        for (int nt = 0; nt < 8; nt++)
#pragma unroll
            for (int i = 0; i < 4; i++) acc[mt][nt][i] = 0.f;

    float4 a_reg[4], b_reg[4];

    auto ldg = [&](int k0) {
#pragma unroll
        for (int p = 0; p < 4; p++) {
            int r = ar + p * 32;
            a_reg[p] = (row0 + r < M)
                           ? *(const float4*)&A[(size_t)(row0 + r) * lda + k0 + ac]
                           : make_float4(0.f, 0.f, 0.f, 0.f);
        }
#pragma unroll
        for (int p = 0; p < 4; p++) {
            int r = brr + p * 8;
            b_reg[p] = *(const float4*)&B[(size_t)(k0 + r) * ldb + col0 + bcc];
        }
    };

    auto sts = [&](int buf) {
        unsigned* as = As + buf * 128 * AP;
        unsigned* bs = Bs + buf * 32 * BP;
#pragma unroll
        for (int p = 0; p < 4; p++) {
            int r = ar + p * 32;
            uint4 u;
            u.x = f2tf(a_reg[p].x); u.y = f2tf(a_reg[p].y);
            u.z = f2tf(a_reg[p].z); u.w = f2tf(a_reg[p].w);
            *(uint4*)&as[r * AP + ac] = u;
        }
#pragma unroll
        for (int p = 0; p < 4; p++) {
            int r = brr + p * 8;
            uint4 u;
            u.x = f2tf(b_reg[p].x); u.y = f2tf(b_reg[p].y);
            u.z = f2tf(b_reg[p].z); u.w = f2tf(b_reg[p].w);
            *(uint4*)&bs[r * BP + bcc] = u;
        }
    };

    ldg(0);
    sts(0);
    __syncthreads();

    const int KT = Ktot >> 5;
    for (int kt = 0; kt < KT; kt++) {
        const int buf = kt & 1;
        if (kt + 1 < KT) ldg((kt + 1) * 32);

        const unsigned* as = As + buf * 128 * AP;
        const unsigned* bs = Bs + buf * 32 * BP;

#pragma unroll
        for (int ks = 0; ks < 4; ks++) {
            unsigned afr[2][4];
#pragma unroll
            for (int mt = 0; mt < 2; mt++) {
                int rb = wr0 + mt * 16;
                int kc = ks * 8 + tig;
                afr[mt][0] = as[(rb + gid) * AP + kc];
                afr[mt][1] = as[(rb + gid + 8) * AP + kc];
                afr[mt][2] = as[(rb + gid) * AP + kc + 4];
                afr[mt][3] = as[(rb + gid + 8) * AP + kc + 4];
            }
#pragma unroll
            for (int nt = 0; nt < 8; nt++) {
                unsigned bfr[2];
                int cb = wc0 + nt * 8 + gid;
                bfr[0] = bs[(ks * 8 + tig) * BP + cb];
                bfr[1] = bs[(ks * 8 + tig + 4) * BP + cb];
#pragma unroll
                for (int mt = 0; mt < 2; mt++) {
                    asm volatile(
                        "mma.sync.aligned.m16n8k8.row.col.f32.tf32.tf32.f32 "
                        "{%0,%1,%2,%3}, {%4,%5,%6,%7}, {%8,%9}, {%0,%1,%2,%3};"
                        : "+f"(acc[mt][nt][0]), "+f"(acc[mt][nt][1]),
                          "+f"(acc[mt][nt][2]), "+f"(acc[mt][nt][3])
                        : "r"(afr[mt][0]), "r"(afr[mt][1]),
                          "r"(afr[mt][2]), "r"(afr[mt][3]),
                          "r"(bfr[0]), "r"(bfr[1]));
                }
            }
        }

        if (kt + 1 < KT) sts(buf ^ 1);
        __syncthreads();
    }

#pragma unroll
    for (int mt = 0; mt < 2; mt++) {
        int r0 = row0 + wr0 + mt * 16 + gid;
#pragma unroll
        for (int nt = 0; nt < 8; nt++) {
            int col = col0 + wc0 + nt * 8 + 2 * tig;
            float b0 = bias[col], b1 = bias[col + 1];
            float v0 = acc[mt][nt][0] + b0;
            float v1 = acc[mt][nt][1] + b1;
            float v2 = acc[mt][nt][2] + b0;
            float v3 = acc[mt][nt][3] + b1;
            if (RELU) {
                v0 = fmaxf(v0, 0.f); v1 = fmaxf(v1, 0.f);
                v2 = fmaxf(v2, 0.f); v3 = fmaxf(v3, 0.f);
            }
            if (r0 < M) {
                if (RESID) {
                    v0 += resid[(size_t)r0 * ldo + col];
                    v1 += resid[(size_t)r0 * ldo + col + 1];
                }
                float2 o; o.x = v0; o.y = v1;
                *(float2*)&out[(size_t)r0 * ldo + col] = o;
            }
            if (r0 + 8 < M) {
                if (RESID) {
                    v2 += resid[(size_t)(r0 + 8) * ldo + col];
                    v3 += resid[(size_t)(r0 + 8) * ldo + col + 1];
                }
                float2 o; o.x = v2; o.y = v3;
                *(float2*)&out[(size_t)(r0 + 8) * ldo + col] = o;
            }
        }
    }
}

template <bool RELU, bool RESID>
__global__ void __launch_bounds__(256, 2)
gemm_tf32(const float* __restrict__ A, int lda,
          const float* __restrict__ B, int ldb,
          const float* __restrict__ bias,
          const float* __restrict__ resid,
          float* __restrict__ out, int ldo,
          int M, int Ktot) {
    extern __shared__ unsigned smem_u[];
    gemm_body<RELU, RESID>(A, lda, B, ldb, bias, resid, out, ldo, M, Ktot,
                           blockIdx.x * 128, blockIdx.y * 128, smem_u);
}

__global__ void __launch_bounds__(256, 2)
qkv_tf32(const float* __restrict__ h,
         const float* __restrict__ Wq, const float* __restrict__ bq,
         const float* __restrict__ Wk, const float* __restrict__ bk,
         const float* __restrict__ Wv, const float* __restrict__ bv,
         float* __restrict__ Q, float* __restrict__ K, float* __restrict__ V) {
    extern __shared__ unsigned smem_u[];
    const float* B;
    const float* bias;
    float* out;
    if (blockIdx.y == 0)      { B = Wq; bias = bq; out = Q; }
    else if (blockIdx.y == 1) { B = Wk; bias = bk; out = K; }
    else                      { B = Wv; bias = bv; out = V; }
    gemm_body<false, false>(h, CC, B, CC, bias, nullptr, out, CC, NN, CC,
                            blockIdx.x * 128, 0, smem_u);
}

// ---------------- launch ----------------------------------------------------
extern "C" void kernel_launch(void* const* d_in, const int* in_sizes, int n_in,
                              void* d_out, int out_size) {
    const float* x     = (const float*)d_in[0];
    const int*   ei    = (const int*)d_in[1];
    const float* Wq    = (const float*)d_in[2];
    const float* bq    = (const float*)d_in[3];
    const float* Wk    = (const float*)d_in[4];
    const float* bk    = (const float*)d_in[5];
    const float* Wv    = (const float*)d_in[6];
    const float* bv    = (const float*)d_in[7];
    const float* Wo    = (const float*)d_in[8];
    const float* bo    = (const float*)d_in[9];
    const float* W1    = (const float*)d_in[10];
    const float* b1    = (const float*)d_in[11];
    const float* W2    = (const float*)d_in[12];
    const float* b2    = (const float*)d_in[13];
    const float* g1    = (const float*)d_in[14];
    const float* beta1 = (const float*)d_in[15];
    const float* g2    = (const float*)d_in[16];
    const float* beta2 = (const float*)d_in[17];
    float*       out   = (float*)d_out;

    float *h, *Q, *K, *V, *aggr, *x2, *hidden;
    int *deg, *off, *cursor, *csr_src;
    cudaGetSymbolAddress((void**)&h,       g_h);
    cudaGetSymbolAddress((void**)&Q,       g_Q);
    cudaGetSymbolAddress((void**)&K,       g_K);
    cudaGetSymbolAddress((void**)&V,       g_V);
    cudaGetSymbolAddress((void**)&aggr,    g_aggr);
    cudaGetSymbolAddress((void**)&x2,      g_x2);
    cudaGetSymbolAddress((void**)&hidden,  g_hidden);
    cudaGetSymbolAddress((void**)&deg,     g_deg);
    cudaGetSymbolAddress((void**)&off,     g_off);
    cudaGetSymbolAddress((void**)&cursor,  g_cursor);
    cudaGetSymbolAddress((void**)&csr_src, g_csr_src);

    const int smem = GEMM_SMEM;  // 71680 B
    cudaFuncSetAttribute(gemm_tf32<false, true>,
                         cudaFuncAttributeMaxDynamicSharedMemorySize, smem);
    cudaFuncSetAttribute(gemm_tf32<true, false>,
                         cudaFuncAttributeMaxDynamicSharedMemorySize, smem);
    cudaFuncSetAttribute(qkv_tf32,
                         cudaFuncAttributeMaxDynamicSharedMemorySize, smem);

    const int gx = (NN + 127) / 128;  // 782

    // CSR build (depends only on edge_index)
    zero_int_kernel<<<(NN + 255) / 256, 256>>>(deg, NN);
    hist_kernel<<<(EE + 255) / 256, 256>>>(ei, deg);
    scan_kernel<<<1, 1024>>>(deg, off, cursor);
    scatter_kernel<<<(EE + 255) / 256, 256>>>(ei, cursor, csr_src);

    // 1) h = LN(x)
    ln_kernel<<<(NN + 7) / 8, 256>>>(x, g1, beta1, h);

    // 2) Q,K,V = h @ W{q,k,v} + b (fused)
    qkv_tf32<<<dim3(gx, 3), 256, smem>>>(h, Wq, bq, Wk, bk, Wv, bv, Q, K, V);

    // 3) aggregate messages per dst (no atomics)
    aggr_kernel<<<(NN + 7) / 8, 256>>>(off, csr_src, Q, K, V, aggr);

    // 4) x2 = aggr @ Wo + bo + x
    gemm_tf32<false, true><<<dim3(gx, 1), 256, smem>>>(
        aggr, CC, Wo, CC, bo, x, x2, CC, NN, CC);

    // 5) h = LN(x2)
    ln_kernel<<<(NN + 7) / 8, 256>>>(x2, g2, beta2, h);

    // 6) hidden = relu(h @ W1 + b1)
    gemm_tf32<true, false><<<dim3(gx, 4), 256, smem>>>(
        h, CC, W1, HIDDEN, b1, nullptr, hidden, HIDDEN, NN, CC);

    // 7) out = hidden @ W2 + b2 + x2
    gemm_tf32<false, true><<<dim3(gx, 1), 256, smem>>>(
        hidden, HIDDEN, W2, CC, b2, x2, out, CC, NN, HIDDEN);
}

// round 6
// speedup vs baseline: 2.5988x; 1.1107x over previous
#include <cuda_runtime.h>

#define NN 100000
#define CC 128
#define EE 600000
#define HIDDEN 512

// ---------------- scratch (device globals; no allocations allowed) ----------
__device__ unsigned g_h[(size_t)NN * CC];        // tf32 bits
__device__ float    g_Q[(size_t)NN * CC];
__device__ float    g_kv[(size_t)NN * 2 * CC];   // packed [K row | V row]
__device__ unsigned g_aggr[(size_t)NN * CC];     // tf32 bits
__device__ float    g_x2[(size_t)NN * CC];
__device__ unsigned g_hidden[(size_t)NN * HIDDEN]; // tf32 bits
__device__ unsigned g_wt[6 * 65536];             // converted weights (worst case)
__device__ int      g_deg[NN];
__device__ int      g_off[NN + 1];
__device__ int      g_cursor[NN];
__device__ int      g_csr_src[EE];

__device__ __forceinline__ unsigned f2tf(float f) {
    unsigned u;
    asm("cvt.rna.tf32.f32 %0, %1;" : "=r"(u) : "f"(f));
    return u;
}

// ---------------- weight conversion (fp32 -> tf32 bits) ---------------------
// layout in g_wt: wq@0, wk@16384, wv@32768, wo@49152, w1@65536, w2@131072
__global__ void wconv_kernel(const float* __restrict__ Wq,
                             const float* __restrict__ Wk,
                             const float* __restrict__ Wv,
                             const float* __restrict__ Wo,
                             const float* __restrict__ W1,
                             const float* __restrict__ W2,
                             unsigned* __restrict__ dst) {
    int i = blockIdx.x * blockDim.x + threadIdx.x;
    if (i >= 196608) return;
    float v;
    if (i < 16384)       v = Wq[i];
    else if (i < 32768)  v = Wk[i - 16384];
    else if (i < 49152)  v = Wv[i - 32768];
    else if (i < 65536)  v = Wo[i - 49152];
    else if (i < 131072) v = W1[i - 65536];
    else                 v = W2[i - 131072];
    dst[i] = f2tf(v);
}

// ---------------- LayerNorm: one warp per row, tf32-bit output --------------
__global__ void ln_kernel(const float* __restrict__ x,
                          const float* __restrict__ g,
                          const float* __restrict__ b,
                          unsigned* __restrict__ out) {
    int row  = blockIdx.x * 8 + (threadIdx.x >> 5);
    int lane = threadIdx.x & 31;
    if (row >= NN) return;
    float4 v = *(const float4*)&x[(size_t)row * CC + lane * 4];
    float s  = v.x + v.y + v.z + v.w;
    float ss = v.x * v.x + v.y * v.y + v.z * v.z + v.w * v.w;
#pragma unroll
    for (int d = 16; d; d >>= 1) {
        s  += __shfl_xor_sync(0xffffffffu, s, d);
        ss += __shfl_xor_sync(0xffffffffu, ss, d);
    }
    float mu  = s * (1.0f / CC);
    float var = ss * (1.0f / CC) - mu * mu;
    float inv = rsqrtf(var + 1e-5f);
    float4 gg = *(const float4*)&g[lane * 4];
    float4 bb = *(const float4*)&b[lane * 4];
    uint4 o;
    o.x = f2tf((v.x - mu) * inv * gg.x + bb.x);
    o.y = f2tf((v.y - mu) * inv * gg.y + bb.y);
    o.z = f2tf((v.z - mu) * inv * gg.z + bb.z);
    o.w = f2tf((v.w - mu) * inv * gg.w + bb.w);
    *(uint4*)&out[(size_t)row * CC + lane * 4] = o;
}

// ---------------- CSR build --------------------------------------------------
__global__ void zero_int_kernel(int* __restrict__ p, int n) {
    int i = blockIdx.x * blockDim.x + threadIdx.x;
    if (i < n) p[i] = 0;
}

__global__ void hist_kernel(const int* __restrict__ ei, int* __restrict__ deg) {
    int e = blockIdx.x * blockDim.x + threadIdx.x;
    if (e < EE) atomicAdd(&deg[ei[EE + e]], 1);
}

__global__ void scan_kernel(const int* __restrict__ deg,
                            int* __restrict__ off,
                            int* __restrict__ cursor) {
    __shared__ int warp_sums[32];
    __shared__ int carry;
    int tid = threadIdx.x, lane = tid & 31, wid = tid >> 5;
    if (tid == 0) carry = 0;
    __syncthreads();
    for (int base = 0; base < NN; base += 1024) {
        int i = base + tid;
        int v = (i < NN) ? deg[i] : 0;
        int x = v;
#pragma unroll
        for (int d = 1; d < 32; d <<= 1) {
            int y = __shfl_up_sync(0xffffffffu, x, d);
            if (lane >= d) x += y;
        }
        if (lane == 31) warp_sums[wid] = x;
        __syncthreads();
        if (wid == 0) {
            int s = warp_sums[lane];
#pragma unroll
            for (int d = 1; d < 32; d <<= 1) {
                int y = __shfl_up_sync(0xffffffffu, s, d);
                if (lane >= d) s += y;
            }
            warp_sums[lane] = s;
        }
        __syncthreads();
        int woff = wid ? warp_sums[wid - 1] : 0;
        int excl = carry + woff + (x - v);
        if (i < NN) { off[i] = excl; cursor[i] = excl; }
        __syncthreads();
        if (tid == 0) carry += warp_sums[31];
        __syncthreads();
    }
    if (threadIdx.x == 0) off[NN] = carry;
}

__global__ void scatter_kernel(const int* __restrict__ ei,
                               int* __restrict__ cursor,
                               int* __restrict__ csr_src) {
    int e = blockIdx.x * blockDim.x + threadIdx.x;
    if (e >= EE) return;
    int dst = ei[EE + e];
    int pos = atomicAdd(&cursor[dst], 1);
    csr_src[pos] = ei[e];
}

// ---------------- aggregation: one warp per dst node, unroll 2 --------------
__device__ __forceinline__ float edge_attn(float4 q, float4 k) {
    float p = q.x * k.x + q.y * k.y + q.z * k.z + q.w * k.w;
    p += __shfl_xor_sync(0xffffffffu, p, 1);
    p += __shfl_xor_sync(0xffffffffu, p, 2);
    float s = p * 0.25f;
    float m = s;
    m = fmaxf(m, __shfl_xor_sync(0xffffffffu, m, 4));
    m = fmaxf(m, __shfl_xor_sync(0xffffffffu, m, 8));
    m = fmaxf(m, __shfl_xor_sync(0xffffffffu, m, 16));
    float ex  = __expf(s - m);
    float sum = ex;
    sum += __shfl_xor_sync(0xffffffffu, sum, 4);
    sum += __shfl_xor_sync(0xffffffffu, sum, 8);
    sum += __shfl_xor_sync(0xffffffffu, sum, 16);
    return ex / sum;
}

__global__ void aggr_kernel(const int* __restrict__ off,
                            const int* __restrict__ csr_src,
                            const float* __restrict__ Q,
                            const float* __restrict__ KV,
                            unsigned* __restrict__ aggr) {
    int n    = blockIdx.x * 8 + (threadIdx.x >> 5);
    int lane = threadIdx.x & 31;
    if (n >= NN) return;
    int s0 = off[n], s1 = off[n + 1];

    float4 q   = *(const float4*)&Q[(size_t)n * CC + lane * 4];
    float4 acc = make_float4(0.f, 0.f, 0.f, 0.f);

    int j = s0;
    for (; j + 1 < s1; j += 2) {
        int src0 = csr_src[j];
        int src1 = csr_src[j + 1];
        const float4* kv0 = (const float4*)&KV[(size_t)src0 * 2 * CC];
        const float4* kv1 = (const float4*)&KV[(size_t)src1 * 2 * CC];
        float4 k0 = kv0[lane];
        float4 v0 = kv0[32 + lane];
        float4 k1 = kv1[lane];
        float4 v1 = kv1[32 + lane];

        float a0 = edge_attn(q, k0);
        acc.x += v0.x * a0; acc.y += v0.y * a0;
        acc.z += v0.z * a0; acc.w += v0.w * a0;
        float a1 = edge_attn(q, k1);
        acc.x += v1.x * a1; acc.y += v1.y * a1;
        acc.z += v1.z * a1; acc.w += v1.w * a1;
    }
    if (j < s1) {
        int src = csr_src[j];
        const float4* kv = (const float4*)&KV[(size_t)src * 2 * CC];
        float4 k = kv[lane];
        float4 v = kv[32 + lane];
        float a = edge_attn(q, k);
        acc.x += v.x * a; acc.y += v.y * a;
        acc.z += v.z * a; acc.w += v.w * a;
    }
    uint4 o;
    o.x = f2tf(acc.x); o.y = f2tf(acc.y);
    o.z = f2tf(acc.z); o.w = f2tf(acc.w);
    *(uint4*)&aggr[(size_t)n * CC + lane * 4] = o;
}

// ---------------- TF32 tensor-core GEMM, cp.async double-buffered -----------
// A, B already in tf32 bit format. out = act(A@B + bias) [+ resid]
// BM=128, BN=128, BK=32; 256 threads = 8 warps (4m x 2n), warp tile 32x64.

#define AP 36
#define BP 136
#define ASZ (128 * AP)
#define BSZ (32 * BP)
#define STG (ASZ + BSZ)
#define GEMM_SMEM (2 * STG * 4)

__device__ __forceinline__ void cp16(unsigned dst, const void* src, bool pred) {
    int sz = pred ? 16 : 0;
    asm volatile("cp.async.cg.shared.global [%0], [%1], 16, %2;\n"
                 :: "r"(dst), "l"(src), "r"(sz));
}

template <bool RELU, bool RESID, bool OUTTF>
__device__ __forceinline__ void gemm_body(
    const unsigned* __restrict__ A, int lda,
    const unsigned* __restrict__ Bw, int ldb,
    const float* __restrict__ bias,
    const float* __restrict__ resid,
    void* __restrict__ outv, int ldo,
    int M, int Ktot, int row0, int col0, unsigned* smem_u) {

    const int tid  = threadIdx.x;
    const int lane = tid & 31;
    const int wid  = tid >> 5;
    const int wr0  = (wid & 3) * 32;
    const int wc0  = (wid >> 2) * 64;
    const int gid  = lane >> 2;
    const int tig  = lane & 3;

    const int ar  = tid >> 3;          // 0..31
    const int ac  = (tid & 7) * 4;     // word offset
    const int brr = tid >> 5;          // 0..7
    const int bcc = (tid & 31) * 4;

    unsigned smem_base = (unsigned)__cvta_generic_to_shared(smem_u);

    auto issue = [&](int kt) {
        int buf = kt & 1;
        unsigned abase = smem_base + buf * STG * 4;
        unsigned bbase = abase + ASZ * 4;
        int k0 = kt * 32;
#pragma unroll
        for (int p = 0; p < 4; p++) {
            int r = ar + p * 32;
            bool pred = (row0 + r < M);
            const unsigned* src = A + (size_t)(pred ? row0 + r : row0) * lda + k0 + ac;
            cp16(abase + (r * AP + ac) * 4, src, pred);
        }
#pragma unroll
        for (int p = 0; p < 4; p++) {
            int r = brr + p * 8;
            const unsigned* src = Bw + (size_t)(k0 + r) * ldb + col0 + bcc;
            cp16(bbase + (r * BP + bcc) * 4, src, true);
        }
    };

    float acc[2][8][4];
#pragma unroll
    for (int mt = 0; mt < 2; mt++)
#pragma unroll
        for (int nt = 0; nt < 8; nt++)
#pragma unroll
            for (int i = 0; i < 4; i++) acc[mt][nt][i] = 0.f;

    issue(0);
    asm volatile("cp.async.commit_group;");

    const int KT = Ktot >> 5;
    for (int kt = 0; kt < KT; kt++) {
        if (kt + 1 < KT) issue(kt + 1);
        asm volatile("cp.async.commit_group;");
        asm volatile("cp.async.wait_group 1;");
        __syncthreads();

        const unsigned* as = smem_u + (kt & 1) * STG;
        const unsigned* bs = as + ASZ;

#pragma unroll
        for (int ks = 0; ks < 4; ks++) {
            unsigned afr[2][4];
#pragma unroll
            for (int mt = 0; mt < 2; mt++) {
                int rb = wr0 + mt * 16;
                int kc = ks * 8 + tig;
                afr[mt][0] = as[(rb + gid) * AP + kc];
                afr[mt][1] = as[(rb + gid + 8) * AP + kc];
                afr[mt][2] = as[(rb + gid) * AP + kc + 4];
                afr[mt][3] = as[(rb + gid + 8) * AP + kc + 4];
            }
#pragma unroll
            for (int nt = 0; nt < 8; nt++) {
                unsigned bfr[2];
                int cb = wc0 + nt * 8 + gid;
                bfr[0] = bs[(ks * 8 + tig) * BP + cb];
                bfr[1] = bs[(ks * 8 + tig + 4) * BP + cb];
#pragma unroll
                for (int mt = 0; mt < 2; mt++) {
                    asm volatile(
                        "mma.sync.aligned.m16n8k8.row.col.f32.tf32.tf32.f32 "
                        "{%0,%1,%2,%3}, {%4,%5,%6,%7}, {%8,%9}, {%0,%1,%2,%3};"
                        : "+f"(acc[mt][nt][0]), "+f"(acc[mt][nt][1]),
                          "+f"(acc[mt][nt][2]), "+f"(acc[mt][nt][3])
                        : "r"(afr[mt][0]), "r"(afr[mt][1]),
                          "r"(afr[mt][2]), "r"(afr[mt][3]),
                          "r"(bfr[0]), "r"(bfr[1]));
                }
            }
        }
        __syncthreads();
    }

    // ---------------- epilogue ----------------
    float*    outf = (float*)outv;
    unsigned* outu = (unsigned*)outv;
#pragma unroll
    for (int mt = 0; mt < 2; mt++) {
        int r0 = row0 + wr0 + mt * 16 + gid;
#pragma unroll
        for (int nt = 0; nt < 8; nt++) {
            int col = col0 + wc0 + nt * 8 + 2 * tig;
            float b0 = bias[col], b1 = bias[col + 1];
            float v0 = acc[mt][nt][0] + b0;
            float v1 = acc[mt][nt][1] + b1;
            float v2 = acc[mt][nt][2] + b0;
            float v3 = acc[mt][nt][3] + b1;
            if (RELU) {
                v0 = fmaxf(v0, 0.f); v1 = fmaxf(v1, 0.f);
                v2 = fmaxf(v2, 0.f); v3 = fmaxf(v3, 0.f);
            }
            if (r0 < M) {
                if (RESID) {
                    v0 += resid[(size_t)r0 * ldo + col];
                    v1 += resid[(size_t)r0 * ldo + col + 1];
                }
                if (OUTTF) {
                    uint2 o; o.x = f2tf(v0); o.y = f2tf(v1);
                    *(uint2*)&outu[(size_t)r0 * ldo + col] = o;
                } else {
                    float2 o; o.x = v0; o.y = v1;
                    *(float2*)&outf[(size_t)r0 * ldo + col] = o;
                }
            }
            if (r0 + 8 < M) {
                if (RESID) {
                    v2 += resid[(size_t)(r0 + 8) * ldo + col];
                    v3 += resid[(size_t)(r0 + 8) * ldo + col + 1];
                }
                if (OUTTF) {
                    uint2 o; o.x = f2tf(v2); o.y = f2tf(v3);
                    *(uint2*)&outu[(size_t)(r0 + 8) * ldo + col] = o;
                } else {
                    float2 o; o.x = v2; o.y = v3;
                    *(float2*)&outf[(size_t)(r0 + 8) * ldo + col] = o;
                }
            }
        }
    }
}

template <bool RELU, bool RESID, bool OUTTF>
__global__ void __launch_bounds__(256, 2)
gemm_tf32(const unsigned* __restrict__ A, int lda,
          const unsigned* __restrict__ Bw, int ldb,
          const float* __restrict__ bias,
          const float* __restrict__ resid,
          void* __restrict__ out, int ldo,
          int M, int Ktot) {
    extern __shared__ unsigned smem_u[];
    gemm_body<RELU, RESID, OUTTF>(A, lda, Bw, ldb, bias, resid, out, ldo,
                                  M, Ktot, blockIdx.x * 128, blockIdx.y * 128,
                                  smem_u);
}

// fused QKV: grid.y selects target; K,V write into packed KV (ldo=256)
__global__ void __launch_bounds__(256, 2)
qkv_tf32(const unsigned* __restrict__ h,
         const unsigned* __restrict__ wt,
         const float* __restrict__ bq,
         const float* __restrict__ bk,
         const float* __restrict__ bv,
         float* __restrict__ Q, float* __restrict__ KV) {
    extern __shared__ unsigned smem_u[];
    const unsigned* Bw;
    const float* bias;
    float* out;
    int ldo;
    if (blockIdx.y == 0)      { Bw = wt;          bias = bq; out = Q;        ldo = CC; }
    else if (blockIdx.y == 1) { Bw = wt + 16384;  bias = bk; out = KV;       ldo = 2 * CC; }
    else                      { Bw = wt + 32768;  bias = bv; out = KV + CC;  ldo = 2 * CC; }
    gemm_body<false, false, false>(h, CC, Bw, CC, bias, nullptr, out, ldo,
                                   NN, CC, blockIdx.x * 128, 0, smem_u);
}

// ---------------- launch ----------------------------------------------------
extern "C" void kernel_launch(void* const* d_in, const int* in_sizes, int n_in,
                              void* d_out, int out_size) {
    const float* x     = (const float*)d_in[0];
    const int*   ei    = (const int*)d_in[1];
    const float* Wq    = (const float*)d_in[2];
    const float* bq    = (const float*)d_in[3];
    const float* Wk    = (const float*)d_in[4];
    const float* bk    = (const float*)d_in[5];
    const float* Wv    = (const float*)d_in[6];
    const float* bv    = (const float*)d_in[7];
    const float* Wo    = (const float*)d_in[8];
    const float* bo    = (const float*)d_in[9];
    const float* W1    = (const float*)d_in[10];
    const float* b1    = (const float*)d_in[11];
    const float* W2    = (const float*)d_in[12];
    const float* b2    = (const float*)d_in[13];
    const float* g1    = (const float*)d_in[14];
    const float* beta1 = (const float*)d_in[15];
    const float* g2    = (const float*)d_in[16];
    const float* beta2 = (const float*)d_in[17];
    float*       out   = (float*)d_out;

    unsigned *h, *aggr, *hidden, *wt;
    float *Q, *KV, *x2;
    int *deg, *off, *cursor, *csr_src;
    cudaGetSymbolAddress((void**)&h,       g_h);
    cudaGetSymbolAddress((void**)&Q,       g_Q);
    cudaGetSymbolAddress((void**)&KV,      g_kv);
    cudaGetSymbolAddress((void**)&aggr,    g_aggr);
    cudaGetSymbolAddress((void**)&x2,      g_x2);
    cudaGetSymbolAddress((void**)&hidden,  g_hidden);
    cudaGetSymbolAddress((void**)&wt,      g_wt);
    cudaGetSymbolAddress((void**)&deg,     g_deg);
    cudaGetSymbolAddress((void**)&off,     g_off);
    cudaGetSymbolAddress((void**)&cursor,  g_cursor);
    cudaGetSymbolAddress((void**)&csr_src, g_csr_src);

    const int smem = GEMM_SMEM;  // 71680 B
    cudaFuncSetAttribute(gemm_tf32<false, true, false>,
                         cudaFuncAttributeMaxDynamicSharedMemorySize, smem);
    cudaFuncSetAttribute(gemm_tf32<true, false, true>,
                         cudaFuncAttributeMaxDynamicSharedMemorySize, smem);
    cudaFuncSetAttribute(qkv_tf32,
                         cudaFuncAttributeMaxDynamicSharedMemorySize, smem);

    const int gx = (NN + 127) / 128;  // 782

    // weights -> tf32 bits (graph-deterministic, runs every call)
    wconv_kernel<<<768, 256>>>(Wq, Wk, Wv, Wo, W1, W2, wt);

    // CSR build
    zero_int_kernel<<<(NN + 255) / 256, 256>>>(deg, NN);
    hist_kernel<<<(EE + 255) / 256, 256>>>(ei, deg);
    scan_kernel<<<1, 1024>>>(deg, off, cursor);
    scatter_kernel<<<(EE + 255) / 256, 256>>>(ei, cursor, csr_src);

    // 1) h = LN(x) (tf32 bits)
    ln_kernel<<<(NN + 7) / 8, 256>>>(x, g1, beta1, h);

    // 2) Q, packed KV
    qkv_tf32<<<dim3(gx, 3), 256, smem>>>(h, wt, bq, bk, bv, Q, KV);

    // 3) per-dst aggregation (tf32-bit output)
    aggr_kernel<<<(NN + 7) / 8, 256>>>(off, csr_src, Q, KV, aggr);

    // 4) x2 = aggr @ Wo + bo + x
    gemm_tf32<false, true, false><<<dim3(gx, 1), 256, smem>>>(
        aggr, CC, wt + 49152, CC, bo, x, x2, CC, NN, CC);

    // 5) h = LN(x2) (tf32 bits)
    ln_kernel<<<(NN + 7) / 8, 256>>>(x2, g2, beta2, h);

    // 6) hidden = relu(h @ W1 + b1) (tf32 bits)
    gemm_tf32<true, false, true><<<dim3(gx, 4), 256, smem>>>(
        h, CC, wt + 65536, HIDDEN, b1, nullptr, hidden, HIDDEN, NN, CC);

    // 7) out = hidden @ W2 + b2 + x2
    gemm_tf32<false, true, false><<<dim3(gx, 1), 256, smem>>>(
        hidden, HIDDEN, wt + 131072, CC, b2, x2, out, CC, NN, HIDDEN);
}

// round 7
// speedup vs baseline: 2.9363x; 1.1298x over previous
#include <cuda_runtime.h>

#define NN 100000
#define CC 128
#define EE 600000
#define HIDDEN 512
#define SCAN_B 1024
#define SCAN_NB ((NN + SCAN_B - 1) / SCAN_B)   // 98

// ---------------- scratch (device globals; no allocations allowed) ----------
__device__ unsigned g_h[(size_t)NN * CC];        // tf32 bits
__device__ float    g_Q[(size_t)NN * CC];
__device__ float    g_kv[(size_t)NN * 2 * CC];   // packed [K row | V row]
__device__ unsigned g_aggr[(size_t)NN * CC];     // tf32 bits
__device__ float    g_x2[(size_t)NN * CC];
__device__ unsigned g_hidden[(size_t)NN * HIDDEN]; // tf32 bits
__device__ unsigned g_wt[6 * 65536];             // converted weights
__device__ int      g_deg[NN];
__device__ int      g_off[NN + 1];
__device__ int      g_cursor[NN];
__device__ int      g_csr_src[EE];
__device__ int      g_bsum[SCAN_NB];

__device__ __forceinline__ unsigned f2tf(float f) {
    unsigned u;
    asm("cvt.rna.tf32.f32 %0, %1;" : "=r"(u) : "f"(f));
    return u;
}

// ---------------- weight conversion (fp32 -> tf32 bits) ---------------------
__global__ void wconv_kernel(const float* __restrict__ Wq,
                             const float* __restrict__ Wk,
                             const float* __restrict__ Wv,
                             const float* __restrict__ Wo,
                             const float* __restrict__ W1,
                             const float* __restrict__ W2,
                             unsigned* __restrict__ dst) {
    int i = blockIdx.x * blockDim.x + threadIdx.x;
    if (i >= 196608) return;
    float v;
    if (i < 16384)       v = Wq[i];
    else if (i < 32768)  v = Wk[i - 16384];
    else if (i < 49152)  v = Wv[i - 32768];
    else if (i < 65536)  v = Wo[i - 49152];
    else if (i < 131072) v = W1[i - 65536];
    else                 v = W2[i - 131072];
    dst[i] = f2tf(v);
}

// ---------------- LayerNorm: one warp per row, tf32-bit output --------------
__global__ void ln_kernel(const float* __restrict__ x,
                          const float* __restrict__ g,
                          const float* __restrict__ b,
                          unsigned* __restrict__ out) {
    int row  = blockIdx.x * 8 + (threadIdx.x >> 5);
    int lane = threadIdx.x & 31;
    if (row >= NN) return;
    float4 v = *(const float4*)&x[(size_t)row * CC + lane * 4];
    float s  = v.x + v.y + v.z + v.w;
    float ss = v.x * v.x + v.y * v.y + v.z * v.z + v.w * v.w;
#pragma unroll
    for (int d = 16; d; d >>= 1) {
        s  += __shfl_xor_sync(0xffffffffu, s, d);
        ss += __shfl_xor_sync(0xffffffffu, ss, d);
    }
    float mu  = s * (1.0f / CC);
    float var = ss * (1.0f / CC) - mu * mu;
    float inv = rsqrtf(var + 1e-5f);
    float4 gg = *(const float4*)&g[lane * 4];
    float4 bb = *(const float4*)&b[lane * 4];
    uint4 o;
    o.x = f2tf((v.x - mu) * inv * gg.x + bb.x);
    o.y = f2tf((v.y - mu) * inv * gg.y + bb.y);
    o.z = f2tf((v.z - mu) * inv * gg.z + bb.z);
    o.w = f2tf((v.w - mu) * inv * gg.w + bb.w);
    *(uint4*)&out[(size_t)row * CC + lane * 4] = o;
}

// ---------------- CSR build --------------------------------------------------
__global__ void zero_int_kernel(int* __restrict__ p, int n) {
    int i = blockIdx.x * blockDim.x + threadIdx.x;
    if (i < n) p[i] = 0;
}

__global__ void hist_kernel(const int* __restrict__ ei, int* __restrict__ deg) {
    int e = blockIdx.x * blockDim.x + threadIdx.x;
    if (e < EE) atomicAdd(&deg[ei[EE + e]], 1);
}

// device-wide exclusive scan, 3 kernels
__global__ void scan_reduce(const int* __restrict__ deg, int* __restrict__ bsum) {
    __shared__ int warp_sums[32];
    int i = blockIdx.x * SCAN_B + threadIdx.x;
    int lane = threadIdx.x & 31, wid = threadIdx.x >> 5;
    int v = (i < NN) ? deg[i] : 0;
#pragma unroll
    for (int d = 16; d; d >>= 1) v += __shfl_xor_sync(0xffffffffu, v, d);
    if (lane == 0) warp_sums[wid] = v;
    __syncthreads();
    if (wid == 0) {
        int s = warp_sums[lane];
#pragma unroll
        for (int d = 16; d; d >>= 1) s += __shfl_xor_sync(0xffffffffu, s, d);
        if (lane == 0) bsum[blockIdx.x] = s;
    }
}

__global__ void scan_tops(int* __restrict__ bsum, int* __restrict__ off) {
    // single block, 128 threads, scans SCAN_NB (<=128) partials exclusively
    __shared__ int warp_sums[4];
    int tid = threadIdx.x, lane = tid & 31, wid = tid >> 5;
    int v = (tid < SCAN_NB) ? bsum[tid] : 0;
    int x = v;
#pragma unroll
    for (int d = 1; d < 32; d <<= 1) {
        int y = __shfl_up_sync(0xffffffffu, x, d);
        if (lane >= d) x += y;
    }
    if (lane == 31) warp_sums[wid] = x;
    __syncthreads();
    if (wid == 0 && lane < 4) {
        int s = warp_sums[lane];
#pragma unroll
        for (int d = 1; d < 4; d <<= 1) {
            int y = __shfl_up_sync(0x0000000fu, s, d);
            if (lane >= d) s += y;
        }
        warp_sums[lane] = s;
    }
    __syncthreads();
    int base = wid ? warp_sums[wid - 1] : 0;
    int excl = base + x - v;
    if (tid < SCAN_NB) bsum[tid] = excl;
    if (tid == 127) off[NN] = base + x;  // grand total (last thread's inclusive)
}

__global__ void scan_apply(const int* __restrict__ deg,
                           const int* __restrict__ bsum,
                           int* __restrict__ off,
                           int* __restrict__ cursor) {
    __shared__ int warp_sums[32];
    int i = blockIdx.x * SCAN_B + threadIdx.x;
    int lane = threadIdx.x & 31, wid = threadIdx.x >> 5;
    int v = (i < NN) ? deg[i] : 0;
    int x = v;
#pragma unroll
    for (int d = 1; d < 32; d <<= 1) {
        int y = __shfl_up_sync(0xffffffffu, x, d);
        if (lane >= d) x += y;
    }
    if (lane == 31) warp_sums[wid] = x;
    __syncthreads();
    if (wid == 0) {
        int s = warp_sums[lane];
#pragma unroll
        for (int d = 1; d < 32; d <<= 1) {
            int y = __shfl_up_sync(0xffffffffu, s, d);
            if (lane >= d) s += y;
        }
        warp_sums[lane] = s;
    }
    __syncthreads();
    int woff = wid ? warp_sums[wid - 1] : 0;
    int excl = bsum[blockIdx.x] + woff + (x - v);
    if (i < NN) { off[i] = excl; cursor[i] = excl; }
}

__global__ void scatter_kernel(const int* __restrict__ ei,
                               int* __restrict__ cursor,
                               int* __restrict__ csr_src) {
    int e = blockIdx.x * blockDim.x + threadIdx.x;
    if (e >= EE) return;
    int dst = ei[EE + e];
    int pos = atomicAdd(&cursor[dst], 1);
    csr_src[pos] = ei[e];
}

// ---------------- aggregation: one warp per dst node, unroll 2 --------------
__device__ __forceinline__ float edge_attn(float4 q, float4 k) {
    float p = q.x * k.x + q.y * k.y + q.z * k.z + q.w * k.w;
    p += __shfl_xor_sync(0xffffffffu, p, 1);
    p += __shfl_xor_sync(0xffffffffu, p, 2);
    float s = p * 0.25f;
    float m = s;
    m = fmaxf(m, __shfl_xor_sync(0xffffffffu, m, 4));
    m = fmaxf(m, __shfl_xor_sync(0xffffffffu, m, 8));
    m = fmaxf(m, __shfl_xor_sync(0xffffffffu, m, 16));
    float ex  = __expf(s - m);
    float sum = ex;
    sum += __shfl_xor_sync(0xffffffffu, sum, 4);
    sum += __shfl_xor_sync(0xffffffffu, sum, 8);
    sum += __shfl_xor_sync(0xffffffffu, sum, 16);
    return ex / sum;
}

__global__ void aggr_kernel(const int* __restrict__ off,
                            const int* __restrict__ csr_src,
                            const float* __restrict__ Q,
                            const float* __restrict__ KV,
                            unsigned* __restrict__ aggr) {
    int n    = blockIdx.x * 8 + (threadIdx.x >> 5);
    int lane = threadIdx.x & 31;
    if (n >= NN) return;
    int s0 = off[n], s1 = off[n + 1];

    float4 q   = *(const float4*)&Q[(size_t)n * CC + lane * 4];
    float4 acc = make_float4(0.f, 0.f, 0.f, 0.f);

    int j = s0;
    for (; j + 1 < s1; j += 2) {
        int src0 = csr_src[j];
        int src1 = csr_src[j + 1];
        const float4* kv0 = (const float4*)&KV[(size_t)src0 * 2 * CC];
        const float4* kv1 = (const float4*)&KV[(size_t)src1 * 2 * CC];
        float4 k0 = kv0[lane];
        float4 v0 = kv0[32 + lane];
        float4 k1 = kv1[lane];
        float4 v1 = kv1[32 + lane];

        float a0 = edge_attn(q, k0);
        acc.x += v0.x * a0; acc.y += v0.y * a0;
        acc.z += v0.z * a0; acc.w += v0.w * a0;
        float a1 = edge_attn(q, k1);
        acc.x += v1.x * a1; acc.y += v1.y * a1;
        acc.z += v1.z * a1; acc.w += v1.w * a1;
    }
    if (j < s1) {
        int src = csr_src[j];
        const float4* kv = (const float4*)&KV[(size_t)src * 2 * CC];
        float4 k = kv[lane];
        float4 v = kv[32 + lane];
        float a = edge_attn(q, k);
        acc.x += v.x * a; acc.y += v.y * a;
        acc.z += v.z * a; acc.w += v.w * a;
    }
    uint4 o;
    o.x = f2tf(acc.x); o.y = f2tf(acc.y);
    o.z = f2tf(acc.z); o.w = f2tf(acc.w);
    *(uint4*)&aggr[(size_t)n * CC + lane * 4] = o;
}

// ---------------- TF32 tensor-core GEMM, cp.async double-buffered -----------
#define AP 36
#define BP 136
#define ASZ (128 * AP)
#define BSZ (32 * BP)
#define STG (ASZ + BSZ)
#define GEMM_SMEM (2 * STG * 4)

__device__ __forceinline__ void cp16(unsigned dst, const void* src, bool pred) {
    int sz = pred ? 16 : 0;
    asm volatile("cp.async.cg.shared.global [%0], [%1], 16, %2;\n"
                 :: "r"(dst), "l"(src), "r"(sz));
}

template <bool RELU, bool RESID, bool OUTTF>
__device__ __forceinline__ void gemm_body(
    const unsigned* __restrict__ A, int lda,
    const unsigned* __restrict__ Bw, int ldb,
    const float* __restrict__ bias,
    const float* __restrict__ resid,
    void* __restrict__ outv, int ldo,
    int M, int Ktot, int row0, int col0, unsigned* smem_u) {

    const int tid  = threadIdx.x;
    const int lane = tid & 31;
    const int wid  = tid >> 5;
    const int wr0  = (wid & 3) * 32;
    const int wc0  = (wid >> 2) * 64;
    const int gid  = lane >> 2;
    const int tig  = lane & 3;

    const int ar  = tid >> 3;
    const int ac  = (tid & 7) * 4;
    const int brr = tid >> 5;
    const int bcc = (tid & 31) * 4;

    unsigned smem_base = (unsigned)__cvta_generic_to_shared(smem_u);

    auto issue = [&](int kt) {
        int buf = kt & 1;
        unsigned abase = smem_base + buf * STG * 4;
        unsigned bbase = abase + ASZ * 4;
        int k0 = kt * 32;
#pragma unroll
        for (int p = 0; p < 4; p++) {
            int r = ar + p * 32;
            bool pred = (row0 + r < M);
            const unsigned* src = A + (size_t)(pred ? row0 + r : row0) * lda + k0 + ac;
            cp16(abase + (r * AP + ac) * 4, src, pred);
        }
#pragma unroll
        for (int p = 0; p < 4; p++) {
            int r = brr + p * 8;
            const unsigned* src = Bw + (size_t)(k0 + r) * ldb + col0 + bcc;
            cp16(bbase + (r * BP + bcc) * 4, src, true);
        }
    };

    float acc[2][8][4];
#pragma unroll
    for (int mt = 0; mt < 2; mt++)
#pragma unroll
        for (int nt = 0; nt < 8; nt++)
#pragma unroll
            for (int i = 0; i < 4; i++) acc[mt][nt][i] = 0.f;

    issue(0);
    asm volatile("cp.async.commit_group;");

    const int KT = Ktot >> 5;
    for (int kt = 0; kt < KT; kt++) {
        if (kt + 1 < KT) issue(kt + 1);
        asm volatile("cp.async.commit_group;");
        asm volatile("cp.async.wait_group 1;");
        __syncthreads();

        const unsigned* as = smem_u + (kt & 1) * STG;
        const unsigned* bs = as + ASZ;

#pragma unroll
        for (int ks = 0; ks < 4; ks++) {
            unsigned afr[2][4];
#pragma unroll
            for (int mt = 0; mt < 2; mt++) {
                int rb = wr0 + mt * 16;
                int kc = ks * 8 + tig;
                afr[mt][0] = as[(rb + gid) * AP + kc];
                afr[mt][1] = as[(rb + gid + 8) * AP + kc];
                afr[mt][2] = as[(rb + gid) * AP + kc + 4];
                afr[mt][3] = as[(rb + gid + 8) * AP + kc + 4];
            }
#pragma unroll
            for (int nt = 0; nt < 8; nt++) {
                unsigned bfr[2];
                int cb = wc0 + nt * 8 + gid;
                bfr[0] = bs[(ks * 8 + tig) * BP + cb];
                bfr[1] = bs[(ks * 8 + tig + 4) * BP + cb];
#pragma unroll
                for (int mt = 0; mt < 2; mt++) {
                    asm volatile(
                        "mma.sync.aligned.m16n8k8.row.col.f32.tf32.tf32.f32 "
                        "{%0,%1,%2,%3}, {%4,%5,%6,%7}, {%8,%9}, {%0,%1,%2,%3};"
                        : "+f"(acc[mt][nt][0]), "+f"(acc[mt][nt][1]),
                          "+f"(acc[mt][nt][2]), "+f"(acc[mt][nt][3])
                        : "r"(afr[mt][0]), "r"(afr[mt][1]),
                          "r"(afr[mt][2]), "r"(afr[mt][3]),
                          "r"(bfr[0]), "r"(bfr[1]));
                }
            }
        }
        __syncthreads();
    }

    float*    outf = (float*)outv;
    unsigned* outu = (unsigned*)outv;
#pragma unroll
    for (int mt = 0; mt < 2; mt++) {
        int r0 = row0 + wr0 + mt * 16 + gid;
#pragma unroll
        for (int nt = 0; nt < 8; nt++) {
            int col = col0 + wc0 + nt * 8 + 2 * tig;
            float b0 = bias[col], b1 = bias[col + 1];
            float v0 = acc[mt][nt][0] + b0;
            float v1 = acc[mt][nt][1] + b1;
            float v2 = acc[mt][nt][2] + b0;
            float v3 = acc[mt][nt][3] + b1;
            if (RELU) {
                v0 = fmaxf(v0, 0.f); v1 = fmaxf(v1, 0.f);
                v2 = fmaxf(v2, 0.f); v3 = fmaxf(v3, 0.f);
            }
            if (r0 < M) {
                if (RESID) {
                    v0 += resid[(size_t)r0 * ldo + col];
                    v1 += resid[(size_t)r0 * ldo + col + 1];
                }
                if (OUTTF) {
                    uint2 o; o.x = f2tf(v0); o.y = f2tf(v1);
                    *(uint2*)&outu[(size_t)r0 * ldo + col] = o;
                } else {
                    float2 o; o.x = v0; o.y = v1;
                    *(float2*)&outf[(size_t)r0 * ldo + col] = o;
                }
            }
            if (r0 + 8 < M) {
                if (RESID) {
                    v2 += resid[(size_t)(r0 + 8) * ldo + col];
                    v3 += resid[(size_t)(r0 + 8) * ldo + col + 1];
                }
                if (OUTTF) {
                    uint2 o; o.x = f2tf(v2); o.y = f2tf(v3);
                    *(uint2*)&outu[(size_t)(r0 + 8) * ldo + col] = o;
                } else {
                    float2 o; o.x = v2; o.y = v3;
                    *(float2*)&outf[(size_t)(r0 + 8) * ldo + col] = o;
                }
            }
        }
    }
}

template <bool RELU, bool RESID, bool OUTTF>
__global__ void __launch_bounds__(256, 2)
gemm_tf32(const unsigned* __restrict__ A, int lda,
          const unsigned* __restrict__ Bw, int ldb,
          const float* __restrict__ bias,
          const float* __restrict__ resid,
          void* __restrict__ out, int ldo,
          int M, int Ktot) {
    extern __shared__ unsigned smem_u[];
    gemm_body<RELU, RESID, OUTTF>(A, lda, Bw, ldb, bias, resid, out, ldo,
                                  M, Ktot, blockIdx.x * 128, blockIdx.y * 128,
                                  smem_u);
}

__global__ void __launch_bounds__(256, 2)
qkv_tf32(const unsigned* __restrict__ h,
         const unsigned* __restrict__ wt,
         const float* __restrict__ bq,
         const float* __restrict__ bk,
         const float* __restrict__ bv,
         float* __restrict__ Q, float* __restrict__ KV) {
    extern __shared__ unsigned smem_u[];
    const unsigned* Bw;
    const float* bias;
    float* out;
    int ldo;
    if (blockIdx.y == 0)      { Bw = wt;          bias = bq; out = Q;        ldo = CC; }
    else if (blockIdx.y == 1) { Bw = wt + 16384;  bias = bk; out = KV;       ldo = 2 * CC; }
    else                      { Bw = wt + 32768;  bias = bv; out = KV + CC;  ldo = 2 * CC; }
    gemm_body<false, false, false>(h, CC, Bw, CC, bias, nullptr, out, ldo,
                                   NN, CC, blockIdx.x * 128, 0, smem_u);
}

// ---------------- launch ----------------------------------------------------
extern "C" void kernel_launch(void* const* d_in, const int* in_sizes, int n_in,
                              void* d_out, int out_size) {
    const float* x     = (const float*)d_in[0];
    const int*   ei    = (const int*)d_in[1];
    const float* Wq    = (const float*)d_in[2];
    const float* bq    = (const float*)d_in[3];
    const float* Wk    = (const float*)d_in[4];
    const float* bk    = (const float*)d_in[5];
    const float* Wv    = (const float*)d_in[6];
    const float* bv    = (const float*)d_in[7];
    const float* Wo    = (const float*)d_in[8];
    const float* bo    = (const float*)d_in[9];
    const float* W1    = (const float*)d_in[10];
    const float* b1    = (const float*)d_in[11];
    const float* W2    = (const float*)d_in[12];
    const float* b2    = (const float*)d_in[13];
    const float* g1    = (const float*)d_in[14];
    const float* beta1 = (const float*)d_in[15];
    const float* g2    = (const float*)d_in[16];
    const float* beta2 = (const float*)d_in[17];
    float*       out   = (float*)d_out;

    unsigned *h, *aggr, *hidden, *wt;
    float *Q, *KV, *x2;
    int *deg, *off, *cursor, *csr_src, *bsum;
    cudaGetSymbolAddress((void**)&h,       g_h);
    cudaGetSymbolAddress((void**)&Q,       g_Q);
    cudaGetSymbolAddress((void**)&KV,      g_kv);
    cudaGetSymbolAddress((void**)&aggr,    g_aggr);
    cudaGetSymbolAddress((void**)&x2,      g_x2);
    cudaGetSymbolAddress((void**)&hidden,  g_hidden);
    cudaGetSymbolAddress((void**)&wt,      g_wt);
    cudaGetSymbolAddress((void**)&deg,     g_deg);
    cudaGetSymbolAddress((void**)&off,     g_off);
    cudaGetSymbolAddress((void**)&cursor,  g_cursor);
    cudaGetSymbolAddress((void**)&csr_src, g_csr_src);
    cudaGetSymbolAddress((void**)&bsum,    g_bsum);

    const int smem = GEMM_SMEM;  // 71680 B
    cudaFuncSetAttribute(gemm_tf32<false, true, false>,
                         cudaFuncAttributeMaxDynamicSharedMemorySize, smem);
    cudaFuncSetAttribute(gemm_tf32<true, false, true>,
                         cudaFuncAttributeMaxDynamicSharedMemorySize, smem);
    cudaFuncSetAttribute(qkv_tf32,
                         cudaFuncAttributeMaxDynamicSharedMemorySize, smem);

    const int gx = (NN + 127) / 128;  // 782

    // weights -> tf32 bits
    wconv_kernel<<<768, 256>>>(Wq, Wk, Wv, Wo, W1, W2, wt);

    // CSR build (device-wide parallel scan)
    zero_int_kernel<<<(NN + 255) / 256, 256>>>(deg, NN);
    hist_kernel<<<(EE + 255) / 256, 256>>>(ei, deg);
    scan_reduce<<<SCAN_NB, SCAN_B>>>(deg, bsum);
    scan_tops<<<1, 128>>>(bsum, off);
    scan_apply<<<SCAN_NB, SCAN_B>>>(deg, bsum, off, cursor);
    scatter_kernel<<<(EE + 255) / 256, 256>>>(ei, cursor, csr_src);

    // 1) h = LN(x) (tf32 bits)
    ln_kernel<<<(NN + 7) / 8, 256>>>(x, g1, beta1, h);

    // 2) Q, packed KV
    qkv_tf32<<<dim3(gx, 3), 256, smem>>>(h, wt, bq, bk, bv, Q, KV);

    // 3) per-dst aggregation (tf32-bit output)
    aggr_kernel<<<(NN + 7) / 8, 256>>>(off, csr_src, Q, KV, aggr);

    // 4) x2 = aggr @ Wo + bo + x
    gemm_tf32<false, true, false><<<dim3(gx, 1), 256, smem>>>(
        aggr, CC, wt + 49152, CC, bo, x, x2, CC, NN, CC);

    // 5) h = LN(x2) (tf32 bits)
    ln_kernel<<<(NN + 7) / 8, 256>>>(x2, g2, beta2, h);

    // 6) hidden = relu(h @ W1 + b1) (tf32 bits)
    gemm_tf32<true, false, true><<<dim3(gx, 4), 256, smem>>>(
        h, CC, wt + 65536, HIDDEN, b1, nullptr, hidden, HIDDEN, NN, CC);

    // 7) out = hidden @ W2 + b2 + x2
    gemm_tf32<false, true, false><<<dim3(gx, 1), 256, smem>>>(
        hidden, HIDDEN, wt + 131072, CC, b2, x2, out, CC, NN, HIDDEN);
}